// round 7
// baseline (speedup 1.0000x reference)
#include <cuda_runtime.h>
#include <cuda_bf16.h>
#include <cstdint>

// Problem constants
#define BB   256
#define NN   512
#define DD   128
#define C1   256          // 2*D
#define C2   128
#define BN_  131072L      // BB*NN

// Scratch (device globals; no cudaMalloc allowed)
__device__ float g_h1[BN_ * C1];
__device__ float g_h2[BN_ * C2];
__device__ float g_stats[768];
__device__ float g_aff[768];
__device__ __nv_bfloat16 g_pt_hi[(long)BB * DD * NN];   // P^T hi, [b][d][j]
__device__ __nv_bfloat16 g_pt_lo[(long)BB * DD * NN];   // P^T lo
__device__ __nv_bfloat16 g_xh[BN_ * C1];                // xcat hi (bf16 split)
__device__ __nv_bfloat16 g_xl[BN_ * C1];                // xcat lo
__device__ __nv_bfloat16 g_w1h[C1 * C1];
__device__ __nv_bfloat16 g_w1l[C1 * C1];
__device__ __nv_bfloat16 g_w2h[C2 * C1];
__device__ __nv_bfloat16 g_w2l[C2 * C1];

__device__ __forceinline__ float lrelu(float v) { return v >= 0.f ? v : 0.01f * v; }

__device__ __forceinline__ uint32_t smem_u32(const void* p) {
    uint32_t a;
    asm("{ .reg .u64 t; cvta.to.shared.u64 t, %1; cvt.u32.u64 %0, t; }" : "=r"(a) : "l"(p));
    return a;
}

// hi = exact-truncation bf16 pair packed via PRMT
__device__ __forceinline__ uint32_t prmt_hi(uint32_t a, uint32_t b) {
    uint32_t r; asm("prmt.b32 %0, %1, %2, 0x7632;" : "=r"(r) : "r"(a), "r"(b)); return r;
}
// packed cvt: low half <- x, high half <- y
__device__ __forceinline__ uint32_t cvt_bf16x2(float x, float y) {
    uint32_t r; asm("cvt.rn.bf16x2.f32 %0, %1, %2;" : "=r"(r) : "f"(y), "f"(x)); return r;
}
__device__ __forceinline__ float trunc_bf(float x) {
    return __uint_as_float(__float_as_uint(x) & 0xFFFF0000u);
}

#define LDMX4(r, addr) \
    asm volatile("ldmatrix.sync.aligned.m8n8.x4.shared.b16 {%0,%1,%2,%3}, [%4];" \
        : "=r"((r)[0]), "=r"((r)[1]), "=r"((r)[2]), "=r"((r)[3]) : "r"(addr))

#define MMA_BF16(d, a, b0v, b1v) \
    asm volatile("mma.sync.aligned.m16n8k16.row.col.f32.bf16.bf16.f32 " \
        "{%0,%1,%2,%3}, {%4,%5,%6,%7}, {%8,%9}, {%0,%1,%2,%3};" \
        : "+f"((d)[0]), "+f"((d)[1]), "+f"((d)[2]), "+f"((d)[3]) \
        : "r"((a)[0]), "r"((a)[1]), "r"((a)[2]), "r"((a)[3]), "r"(b0v), "r"(b1v))

// dynamic smem layout (shared by all HMMA kernels): one 64 KB stage
#define SA_HI   0
#define SA_LO   16384
#define SB_HI   32768
#define SB_LO   49152
// aggr extras
#define SM_PART 65536
#define SM_RINV 66560
#define SM_TOT  67072
// gemm1 extras
#define SG_SUM  65536
#define SG_SQ   66048
#define SG_TOT  66560
// gemm2 extras
#define S2_AFF  65536          // 2 x 256 floats = 2048 B
#define S2_SUM  67584
#define S2_SQ   68096
#define S2_TOT  68608

extern __shared__ __align__(1024) char dsm[];

// ---------------------------------------------------------------------------
// Shared consumer: one K=64 chunk, 3-pass bf16-split HMMA into acc[2][8][4]
// ---------------------------------------------------------------------------
__device__ __forceinline__ void consume64(uint32_t aA_base, uint32_t bB_base,
                                          int a_kb, uint32_t a_xm,
                                          int b_kb, uint32_t b_xm,
                                          float (&acc)[2][8][4]) {
    #pragma unroll
    for (int ks = 0; ks < 4; ks++) {
        const uint32_t kA = ((uint32_t)(ks * 32 + a_kb)) ^ a_xm;
        uint32_t ah[2][4], al[2][4];
        LDMX4(ah[0], aA_base + SA_HI + kA);
        LDMX4(ah[1], aA_base + SA_HI + 2048 + kA);
        LDMX4(al[0], aA_base + SA_LO + kA);
        LDMX4(al[1], aA_base + SA_LO + 2048 + kA);

        const uint32_t kB = ((uint32_t)(ks * 32 + b_kb)) ^ b_xm;
        #pragma unroll
        for (int nh = 0; nh < 2; nh++) {
            uint32_t bh[2][4], bl[2][4];
            LDMX4(bh[0], bB_base + SB_HI + (uint32_t)(nh * 32 * 128) + kB);
            LDMX4(bh[1], bB_base + SB_HI + (uint32_t)((nh * 32 + 16) * 128) + kB);
            LDMX4(bl[0], bB_base + SB_LO + (uint32_t)(nh * 32 * 128) + kB);
            LDMX4(bl[1], bB_base + SB_LO + (uint32_t)((nh * 32 + 16) * 128) + kB);
            #pragma unroll
            for (int nf4 = 0; nf4 < 4; nf4++) {
                const int qq = nf4 >> 1, hh = (nf4 & 1) * 2;
                const int nf = nh * 4 + nf4;
                #pragma unroll
                for (int mf = 0; mf < 2; mf++) {
                    MMA_BF16(acc[mf][nf], ah[mf], bh[qq][hh], bh[qq][hh + 1]);
                    MMA_BF16(acc[mf][nf], ah[mf], bl[qq][hh], bl[qq][hh + 1]);
                    MMA_BF16(acc[mf][nf], al[mf], bh[qq][hh], bh[qq][hh + 1]);
                }
            }
        }
    }
}

// ---------------------------------------------------------------------------
// K0: zero stats accumulators
// ---------------------------------------------------------------------------
__global__ void k_zero() {
    int t = threadIdx.x;
    if (t < 768) g_stats[t] = 0.f;
}

// ---------------------------------------------------------------------------
// Kp: transpose P -> Pt_hi / Pt_lo (bf16 split), [b][d][j]
// ---------------------------------------------------------------------------
__global__ __launch_bounds__(256) void k_prep(const float* __restrict__ P) {
    __shared__ float s[32][33];
    int b = blockIdx.z, j0 = blockIdx.x * 32, d0 = blockIdx.y * 32;
    int t = threadIdx.x;
    {
        int jr = t >> 3, dq = (t & 7) * 4;
        float4 v = *(const float4*)(P + ((long)b * NN + j0 + jr) * DD + d0 + dq);
        s[jr][dq + 0] = v.x; s[jr][dq + 1] = v.y; s[jr][dq + 2] = v.z; s[jr][dq + 3] = v.w;
    }
    __syncthreads();
    int d = t >> 3, jq = (t & 7) * 4;
    float x0 = s[jq + 0][d], x1 = s[jq + 1][d], x2 = s[jq + 2][d], x3 = s[jq + 3][d];
    uint32_t h01 = prmt_hi(__float_as_uint(x0), __float_as_uint(x1));
    uint32_t h23 = prmt_hi(__float_as_uint(x2), __float_as_uint(x3));
    uint32_t l01 = cvt_bf16x2(x0 - trunc_bf(x0), x1 - trunc_bf(x1));
    uint32_t l23 = cvt_bf16x2(x2 - trunc_bf(x2), x3 - trunc_bf(x3));
    long off = ((long)b * DD + d0 + d) * NN + j0 + jq;
    *(uint2*)(g_pt_hi + off) = make_uint2(h01, h23);
    *(uint2*)(g_pt_lo + off) = make_uint2(l01, l23);
}

// ---------------------------------------------------------------------------
// Kw: split W1 / W2 into bf16 hi/lo
// ---------------------------------------------------------------------------
__global__ __launch_bounds__(256) void k_wsplit(const float* __restrict__ W1,
                                                const float* __restrict__ W2) {
    int i = blockIdx.x * 256 + threadIdx.x;
    if (i < C1 * C1) {
        float f = W1[i];
        ((unsigned short*)g_w1h)[i] = (unsigned short)(__float_as_uint(f) >> 16);
        g_w1l[i] = __float2bfloat16(f - trunc_bf(f));
    } else if (i < C1 * C1 + C2 * C1) {
        int j = i - C1 * C1;
        float f = W2[j];
        ((unsigned short*)g_w2h)[j] = (unsigned short)(__float_as_uint(f) >> 16);
        g_w2l[j] = __float2bfloat16(f - trunc_bf(f));
    }
}

// ---------------------------------------------------------------------------
// K1: bf16-split HMMA aggr.  Epilogue: L1 row norm -> split bf16 store.
// ---------------------------------------------------------------------------
__global__ __launch_bounds__(256, 2) void k_aggr(const float* __restrict__ Ed,
                                                 const float* __restrict__ Ei) {
    const uint32_t sb = smem_u32(dsm);
    const int tid = threadIdx.x;
    const int lane = tid & 31, wid = tid >> 5;
    const int wr = wid >> 1, wc = wid & 1;
    const int b = blockIdx.y, i0 = blockIdx.x * 128, edge = blockIdx.z;
    const float* E = edge ? Ei : Ed;

    const int r = tid >> 1;
    const int colbase = (tid & 1) * 32;
    const int irow = i0 + r;
    const float* Erow = E + ((long)b * NN + irow) * NN + colbase;
    const __nv_bfloat16* Bh = g_pt_hi + ((long)b * DD + r) * NN + colbase;
    const __nv_bfloat16* Bl = g_pt_lo + ((long)b * DD + r) * NN + colbase;
    float rs = 0.f;

    const int a_rin = (lane & 7) + ((lane >> 3) & 1) * 8;
    const int a_kb  = ((lane >> 3) >> 1) * 16;
    const int a_row = wr * 32 + a_rin;
    const uint32_t a_xm = (uint32_t)((a_row & 7) << 4);
    const uint32_t aA_base = sb + (uint32_t)(a_row * 128);

    const int b_nin = (lane & 7) + (lane >= 16 ? 8 : 0);
    const int b_kb  = ((lane >> 3) & 1) * 16;
    const uint32_t b_xm = (uint32_t)(((b_nin & 7)) << 4);
    const uint32_t bB_base = sb + (uint32_t)((wc * 64 + b_nin) * 128);

    float acc[2][8][4];
    #pragma unroll
    for (int mf = 0; mf < 2; mf++)
        #pragma unroll
        for (int nf = 0; nf < 8; nf++)
            #pragma unroll
            for (int q = 0; q < 4; q++) acc[mf][nf][q] = 0.f;

    for (int c = 0; c < 8; c++) {
        const int k0 = c * 64;

        float4 v[8];
        #pragma unroll
        for (int u = 0; u < 8; u++) v[u] = *(const float4*)(Erow + k0 + u * 4);
        #pragma unroll
        for (int u = 0; u < 8; u++) {
            int jb = k0 + colbase + u * 4;
            if (jb + 0 == irow) v[u].x = 0.f;
            if (jb + 1 == irow) v[u].y = 0.f;
            if (jb + 2 == irow) v[u].z = 0.f;
            if (jb + 3 == irow) v[u].w = 0.f;
            rs += v[u].x + v[u].y + v[u].z + v[u].w;
        }
        #pragma unroll
        for (int u2 = 0; u2 < 4; u2++) {
            float4 a = v[2 * u2], q = v[2 * u2 + 1];
            uint4 hv = make_uint4(
                prmt_hi(__float_as_uint(a.x), __float_as_uint(a.y)),
                prmt_hi(__float_as_uint(a.z), __float_as_uint(a.w)),
                prmt_hi(__float_as_uint(q.x), __float_as_uint(q.y)),
                prmt_hi(__float_as_uint(q.z), __float_as_uint(q.w)));
            uint4 lv = make_uint4(
                cvt_bf16x2(a.x - trunc_bf(a.x), a.y - trunc_bf(a.y)),
                cvt_bf16x2(a.z - trunc_bf(a.z), a.w - trunc_bf(a.w)),
                cvt_bf16x2(q.x - trunc_bf(q.x), q.y - trunc_bf(q.y)),
                cvt_bf16x2(q.z - trunc_bf(q.z), q.w - trunc_bf(q.w)));
            uint32_t off = r * 128 + colbase * 2 + u2 * 16;
            uint32_t sw = off ^ ((off >> 3) & 0x70);
            *(uint4*)(dsm + SA_HI + sw) = hv;
            *(uint4*)(dsm + SA_LO + sw) = lv;
        }
        #pragma unroll
        for (int u2 = 0; u2 < 4; u2++) {
            uint4 hv = *(const uint4*)(Bh + k0 + u2 * 8);
            uint4 lv = *(const uint4*)(Bl + k0 + u2 * 8);
            uint32_t off = r * 128 + colbase * 2 + u2 * 16;
            uint32_t sw = off ^ ((off >> 3) & 0x70);
            *(uint4*)(dsm + SB_HI + sw) = hv;
            *(uint4*)(dsm + SB_LO + sw) = lv;
        }
        __syncthreads();
        consume64(aA_base, bB_base, a_kb, a_xm, b_kb, b_xm, acc);
        __syncthreads();
    }

    // row sums -> inverse
    ((float*)(dsm + SM_PART))[tid] = rs;
    __syncthreads();
    if (tid < 128) {
        float s = ((float*)(dsm + SM_PART))[2 * tid] + ((float*)(dsm + SM_PART))[2 * tid + 1];
        ((float*)(dsm + SM_RINV))[tid] = 1.f / fmaxf(s, 1e-12f);
    }
    __syncthreads();

    // epilogue: scale + split bf16 store
    const float* rinv = (const float*)(dsm + SM_RINV);
    #pragma unroll
    for (int mf = 0; mf < 2; mf++) {
        const int lr0 = wr * 32 + mf * 16 + (lane >> 2);
        const float inv0 = rinv[lr0], inv1 = rinv[lr0 + 8];
        long idx0 = ((long)(b * NN + i0 + lr0)) * C1 + edge * 128 + wc * 64 + 2 * (lane & 3);
        long idx1 = idx0 + 8L * C1;
        #pragma unroll
        for (int nf = 0; nf < 8; nf++) {
            float x0 = acc[mf][nf][0] * inv0, x1 = acc[mf][nf][1] * inv0;
            float y0 = acc[mf][nf][2] * inv1, y1 = acc[mf][nf][3] * inv1;
            *(uint32_t*)(g_xh + idx0 + nf * 8) = prmt_hi(__float_as_uint(x0), __float_as_uint(x1));
            *(uint32_t*)(g_xl + idx0 + nf * 8) = cvt_bf16x2(x0 - trunc_bf(x0), x1 - trunc_bf(x1));
            *(uint32_t*)(g_xh + idx1 + nf * 8) = prmt_hi(__float_as_uint(y0), __float_as_uint(y1));
            *(uint32_t*)(g_xl + idx1 + nf * 8) = cvt_bf16x2(y0 - trunc_bf(y0), y1 - trunc_bf(y1));
        }
    }
}

// ---------------------------------------------------------------------------
// K2: HMMA gemm1: h1 = xcat @ W1^T, + per-channel BN stats.
// grid (2 n-blocks, 1024 m-blocks) — n fastest so both n-blocks share A in L2.
// ---------------------------------------------------------------------------
__global__ __launch_bounds__(256, 2) void k_gemm1h() {
    const uint32_t sb = smem_u32(dsm);
    const int tid = threadIdx.x;
    const int lane = tid & 31, wid = tid >> 5;
    const int wr = wid >> 1, wc = wid & 1;
    const long m0 = (long)blockIdx.y * 128;
    const int n0 = blockIdx.x * 128;

    const int r = tid >> 1;
    const int kb = (tid & 1) * 32;
    const __nv_bfloat16* Ah = g_xh + (m0 + r) * C1 + kb;
    const __nv_bfloat16* Al = g_xl + (m0 + r) * C1 + kb;
    const __nv_bfloat16* Bh = g_w1h + (long)(n0 + r) * C1 + kb;
    const __nv_bfloat16* Bl = g_w1l + (long)(n0 + r) * C1 + kb;

    const int a_rin = (lane & 7) + ((lane >> 3) & 1) * 8;
    const int a_kb  = ((lane >> 3) >> 1) * 16;
    const int a_row = wr * 32 + a_rin;
    const uint32_t a_xm = (uint32_t)((a_row & 7) << 4);
    const uint32_t aA_base = sb + (uint32_t)(a_row * 128);

    const int b_nin = (lane & 7) + (lane >= 16 ? 8 : 0);
    const int b_kb  = ((lane >> 3) & 1) * 16;
    const uint32_t b_xm = (uint32_t)(((b_nin & 7)) << 4);
    const uint32_t bB_base = sb + (uint32_t)((wc * 64 + b_nin) * 128);

    float* ssum = (float*)(dsm + SG_SUM);
    float* ssq  = (float*)(dsm + SG_SQ);
    if (tid < 128) { ssum[tid] = 0.f; ssq[tid] = 0.f; }

    float acc[2][8][4];
    #pragma unroll
    for (int mf = 0; mf < 2; mf++)
        #pragma unroll
        for (int nf = 0; nf < 8; nf++)
            #pragma unroll
            for (int q = 0; q < 4; q++) acc[mf][nf][q] = 0.f;

    for (int c = 0; c < 4; c++) {
        const int k0 = c * 64;
        #pragma unroll
        for (int u2 = 0; u2 < 4; u2++) {
            uint4 ahv = *(const uint4*)(Ah + k0 + u2 * 8);
            uint4 alv = *(const uint4*)(Al + k0 + u2 * 8);
            uint4 bhv = *(const uint4*)(Bh + k0 + u2 * 8);
            uint4 blv = *(const uint4*)(Bl + k0 + u2 * 8);
            uint32_t off = r * 128 + kb * 2 + u2 * 16;
            uint32_t sw = off ^ ((off >> 3) & 0x70);
            *(uint4*)(dsm + SA_HI + sw) = ahv;
            *(uint4*)(dsm + SA_LO + sw) = alv;
            *(uint4*)(dsm + SB_HI + sw) = bhv;
            *(uint4*)(dsm + SB_LO + sw) = blv;
        }
        __syncthreads();
        consume64(aA_base, bB_base, a_kb, a_xm, b_kb, b_xm, acc);
        __syncthreads();
    }

    // store h1 + stats
    #pragma unroll
    for (int mf = 0; mf < 2; mf++) {
        const int lr0 = wr * 32 + mf * 16 + (lane >> 2);
        float* d0 = g_h1 + (m0 + lr0) * C1 + n0 + wc * 64 + 2 * (lane & 3);
        float* d1 = d0 + 8L * C1;
        #pragma unroll
        for (int nf = 0; nf < 8; nf++) {
            *(float2*)(d0 + nf * 8) = make_float2(acc[mf][nf][0], acc[mf][nf][1]);
            *(float2*)(d1 + nf * 8) = make_float2(acc[mf][nf][2], acc[mf][nf][3]);
        }
    }
    #pragma unroll
    for (int nf = 0; nf < 8; nf++) {
        #pragma unroll
        for (int par = 0; par < 2; par++) {
            float v0 = acc[0][nf][par], v1 = acc[0][nf][par + 2];
            float v2 = acc[1][nf][par], v3 = acc[1][nf][par + 2];
            float s = v0 + v1 + v2 + v3;
            float q = v0 * v0 + v1 * v1 + v2 * v2 + v3 * v3;
            #pragma unroll
            for (int m = 4; m <= 16; m <<= 1) {
                s += __shfl_xor_sync(0xffffffffu, s, m);
                q += __shfl_xor_sync(0xffffffffu, q, m);
            }
            if (lane < 4) {
                int ch = wc * 64 + nf * 8 + 2 * lane + par;
                atomicAdd(&ssum[ch], s);
                atomicAdd(&ssq[ch], q);
            }
        }
    }
    __syncthreads();
    if (tid < 128) {
        atomicAdd(&g_stats[n0 + tid], ssum[tid]);
        atomicAdd(&g_stats[256 + n0 + tid], ssq[tid]);
    }
}

// ---------------------------------------------------------------------------
// K3/K5: stats -> (scale, shift)
// ---------------------------------------------------------------------------
__global__ void k_bnaff(const float* __restrict__ g, const float* __restrict__ b,
                        int C, int statoff, int affoff) {
    int o = threadIdx.x;
    if (o < C) {
        const float inv_cnt = 1.f / 131072.f;
        float mean = g_stats[statoff + o] * inv_cnt;
        float var  = g_stats[statoff + C + o] * inv_cnt - mean * mean;
        float sc = g[o] * rsqrtf(var + 1e-5f);
        g_aff[affoff + o]     = sc;
        g_aff[affoff + C + o] = b[o] - mean * sc;
    }
}

// ---------------------------------------------------------------------------
// K4: HMMA gemm2: h2 = lrelu(affine1(h1)) @ W2^T, + BN2 stats.
// ---------------------------------------------------------------------------
__global__ __launch_bounds__(256, 2) void k_gemm2h() {
    const uint32_t sb = smem_u32(dsm);
    const int tid = threadIdx.x;
    const int lane = tid & 31, wid = tid >> 5;
    const int wr = wid >> 1, wc = wid & 1;
    const long m0 = (long)blockIdx.x * 128;

    const int r = tid >> 1;
    const int kb = (tid & 1) * 32;
    const float* Arow = g_h1 + (m0 + r) * C1 + kb;
    const __nv_bfloat16* Bh = g_w2h + (long)r * C1 + kb;
    const __nv_bfloat16* Bl = g_w2l + (long)r * C1 + kb;

    const int a_rin = (lane & 7) + ((lane >> 3) & 1) * 8;
    const int a_kb  = ((lane >> 3) >> 1) * 16;
    const int a_row = wr * 32 + a_rin;
    const uint32_t a_xm = (uint32_t)((a_row & 7) << 4);
    const uint32_t aA_base = sb + (uint32_t)(a_row * 128);

    const int b_nin = (lane & 7) + (lane >= 16 ? 8 : 0);
    const int b_kb  = ((lane >> 3) & 1) * 16;
    const uint32_t b_xm = (uint32_t)(((b_nin & 7)) << 4);
    const uint32_t bB_base = sb + (uint32_t)((wc * 64 + b_nin) * 128);

    float* saff0 = (float*)(dsm + S2_AFF);
    float* saff1 = saff0 + 256;
    float* ssum  = (float*)(dsm + S2_SUM);
    float* ssq   = (float*)(dsm + S2_SQ);
    saff0[tid] = g_aff[tid];
    saff1[tid] = g_aff[256 + tid];
    if (tid < 128) { ssum[tid] = 0.f; ssq[tid] = 0.f; }
    __syncthreads();

    float acc[2][8][4];
    #pragma unroll
    for (int mf = 0; mf < 2; mf++)
        #pragma unroll
        for (int nf = 0; nf < 8; nf++)
            #pragma unroll
            for (int q = 0; q < 4; q++) acc[mf][nf][q] = 0.f;

    for (int c = 0; c < 4; c++) {
        const int k0 = c * 64;
        float4 v[8];
        #pragma unroll
        for (int u = 0; u < 8; u++) v[u] = *(const float4*)(Arow + k0 + u * 4);
        #pragma unroll
        for (int u = 0; u < 8; u++) {
            int ch = kb + k0 + u * 4;
            v[u].x = lrelu(saff0[ch + 0] * v[u].x + saff1[ch + 0]);
            v[u].y = lrelu(saff0[ch + 1] * v[u].y + saff1[ch + 1]);
            v[u].z = lrelu(saff0[ch + 2] * v[u].z + saff1[ch + 2]);
            v[u].w = lrelu(saff0[ch + 3] * v[u].w + saff1[ch + 3]);
        }
        #pragma unroll
        for (int u2 = 0; u2 < 4; u2++) {
            float4 a = v[2 * u2], q = v[2 * u2 + 1];
            uint4 hv = make_uint4(
                prmt_hi(__float_as_uint(a.x), __float_as_uint(a.y)),
                prmt_hi(__float_as_uint(a.z), __float_as_uint(a.w)),
                prmt_hi(__float_as_uint(q.x), __float_as_uint(q.y)),
                prmt_hi(__float_as_uint(q.z), __float_as_uint(q.w)));
            uint4 lv = make_uint4(
                cvt_bf16x2(a.x - trunc_bf(a.x), a.y - trunc_bf(a.y)),
                cvt_bf16x2(a.z - trunc_bf(a.z), a.w - trunc_bf(a.w)),
                cvt_bf16x2(q.x - trunc_bf(q.x), q.y - trunc_bf(q.y)),
                cvt_bf16x2(q.z - trunc_bf(q.z), q.w - trunc_bf(q.w)));
            uint32_t off = r * 128 + kb * 2 + u2 * 16;
            uint32_t sw = off ^ ((off >> 3) & 0x70);
            *(uint4*)(dsm + SA_HI + sw) = hv;
            *(uint4*)(dsm + SA_LO + sw) = lv;
            uint4 bhv = *(const uint4*)(Bh + k0 + u2 * 8);
            uint4 blv = *(const uint4*)(Bl + k0 + u2 * 8);
            *(uint4*)(dsm + SB_HI + sw) = bhv;
            *(uint4*)(dsm + SB_LO + sw) = blv;
        }
        __syncthreads();
        consume64(aA_base, bB_base, a_kb, a_xm, b_kb, b_xm, acc);
        __syncthreads();
    }

    // store h2 + stats
    #pragma unroll
    for (int mf = 0; mf < 2; mf++) {
        const int lr0 = wr * 32 + mf * 16 + (lane >> 2);
        float* d0 = g_h2 + (m0 + lr0) * C2 + wc * 64 + 2 * (lane & 3);
        float* d1 = d0 + 8L * C2;
        #pragma unroll
        for (int nf = 0; nf < 8; nf++) {
            *(float2*)(d0 + nf * 8) = make_float2(acc[mf][nf][0], acc[mf][nf][1]);
            *(float2*)(d1 + nf * 8) = make_float2(acc[mf][nf][2], acc[mf][nf][3]);
        }
    }
    #pragma unroll
    for (int nf = 0; nf < 8; nf++) {
        #pragma unroll
        for (int par = 0; par < 2; par++) {
            float v0 = acc[0][nf][par], v1 = acc[0][nf][par + 2];
            float v2 = acc[1][nf][par], v3 = acc[1][nf][par + 2];
            float s = v0 + v1 + v2 + v3;
            float q = v0 * v0 + v1 * v1 + v2 * v2 + v3 * v3;
            #pragma unroll
            for (int m = 4; m <= 16; m <<= 1) {
                s += __shfl_xor_sync(0xffffffffu, s, m);
                q += __shfl_xor_sync(0xffffffffu, q, m);
            }
            if (lane < 4) {
                int ch = wc * 64 + nf * 8 + 2 * lane + par;
                atomicAdd(&ssum[ch], s);
                atomicAdd(&ssq[ch], q);
            }
        }
    }
    __syncthreads();
    if (tid < 128) {
        atomicAdd(&g_stats[512 + tid], ssum[tid]);
        atomicAdd(&g_stats[640 + tid], ssq[tid]);
    }
}

// ---------------------------------------------------------------------------
// K6: out = lrelu(scale2*h2 + shift2)
// ---------------------------------------------------------------------------
__global__ __launch_bounds__(256) void k_final(float* __restrict__ out) {
    long idx = ((long)blockIdx.x * blockDim.x + threadIdx.x);
    long e = idx * 4;
    int ch = (int)(e & 127);
    float4 v = *(const float4*)&g_h2[e];
    v.x = lrelu(g_aff[512 + ch + 0] * v.x + g_aff[640 + ch + 0]);
    v.y = lrelu(g_aff[512 + ch + 1] * v.y + g_aff[640 + ch + 1]);
    v.z = lrelu(g_aff[512 + ch + 2] * v.z + g_aff[640 + ch + 2]);
    v.w = lrelu(g_aff[512 + ch + 3] * v.w + g_aff[640 + ch + 3]);
    *(float4*)&out[e] = v;
}

// ---------------------------------------------------------------------------
extern "C" void kernel_launch(void* const* d_in, const int* in_sizes, int n_in,
                              void* d_out, int out_size) {
    const float* Ed = (const float*)d_in[0];
    const float* Ei = (const float*)d_in[1];
    const float* P  = (const float*)d_in[2];
    const float* W1 = (const float*)d_in[3];
    const float* g1 = (const float*)d_in[4];
    const float* b1 = (const float*)d_in[5];
    const float* W2 = (const float*)d_in[6];
    const float* g2 = (const float*)d_in[7];
    const float* b2 = (const float*)d_in[8];
    float* out = (float*)d_out;

    cudaFuncSetAttribute((const void*)k_aggr,
                         cudaFuncAttributeMaxDynamicSharedMemorySize, SM_TOT);
    cudaFuncSetAttribute((const void*)k_gemm1h,
                         cudaFuncAttributeMaxDynamicSharedMemorySize, SG_TOT);
    cudaFuncSetAttribute((const void*)k_gemm2h,
                         cudaFuncAttributeMaxDynamicSharedMemorySize, S2_TOT);

    k_zero<<<1, 768>>>();
    k_prep<<<dim3(16, 4, 256), 256>>>(P);
    k_wsplit<<<384, 256>>>(W1, W2);
    k_aggr<<<dim3(4, 256, 2), 256, SM_TOT>>>(Ed, Ei);
    k_gemm1h<<<dim3(2, 1024), 256, SG_TOT>>>();
    k_bnaff<<<1, 256>>>(g1, b1, 256, 0, 0);
    k_gemm2h<<<1024, 256, S2_TOT>>>();
    k_bnaff<<<1, 128>>>(g2, b2, 128, 512, 512);
    k_final<<<(int)(BN_ * C2 / 4 / 256), 256>>>(out);
}

// round 8
// speedup vs baseline: 1.8947x; 1.8947x over previous
#include <cuda_runtime.h>
#include <cuda_bf16.h>
#include <cstdint>

// Problem constants
#define BB   256
#define NN   512
#define DD   128
#define C1   256          // 2*D
#define C2   128
#define BN_  131072L      // BB*NN

// Scratch (device globals; no cudaMalloc allowed)
__device__ float g_h1[BN_ * C1];
__device__ float g_h2[BN_ * C2];
__device__ float g_stats[768];
__device__ float g_aff[768];
__device__ __nv_bfloat16 g_pt_hi[(long)BB * DD * NN];   // P^T hi, [b][d][j]
__device__ __nv_bfloat16 g_pt_lo[(long)BB * DD * NN];   // P^T lo
__device__ __nv_bfloat16 g_xh[BN_ * C1];                // xcat hi (bf16 split)
__device__ __nv_bfloat16 g_xl[BN_ * C1];                // xcat lo
__device__ __nv_bfloat16 g_w1h[C1 * C1];
__device__ __nv_bfloat16 g_w1l[C1 * C1];
__device__ __nv_bfloat16 g_w2h[C2 * C1];
__device__ __nv_bfloat16 g_w2l[C2 * C1];

__device__ __forceinline__ float lrelu(float v) { return v >= 0.f ? v : 0.01f * v; }

__device__ __forceinline__ uint32_t smem_u32(const void* p) {
    uint32_t a;
    asm("{ .reg .u64 t; cvta.to.shared.u64 t, %1; cvt.u32.u64 %0, t; }" : "=r"(a) : "l"(p));
    return a;
}

// hi = exact-truncation bf16 pair packed via PRMT
__device__ __forceinline__ uint32_t prmt_hi(uint32_t a, uint32_t b) {
    uint32_t r; asm("prmt.b32 %0, %1, %2, 0x7632;" : "=r"(r) : "r"(a), "r"(b)); return r;
}
// packed cvt: low half <- x, high half <- y
__device__ __forceinline__ uint32_t cvt_bf16x2(float x, float y) {
    uint32_t r; asm("cvt.rn.bf16x2.f32 %0, %1, %2;" : "=r"(r) : "f"(y), "f"(x)); return r;
}
__device__ __forceinline__ float trunc_bf(float x) {
    return __uint_as_float(__float_as_uint(x) & 0xFFFF0000u);
}

#define LDMX4(r, addr) \
    asm volatile("ldmatrix.sync.aligned.m8n8.x4.shared.b16 {%0,%1,%2,%3}, [%4];" \
        : "=r"((r)[0]), "=r"((r)[1]), "=r"((r)[2]), "=r"((r)[3]) : "r"(addr))

#define MMA_BF16(d, a, b0v, b1v) \
    asm volatile("mma.sync.aligned.m16n8k16.row.col.f32.bf16.bf16.f32 " \
        "{%0,%1,%2,%3}, {%4,%5,%6,%7}, {%8,%9}, {%0,%1,%2,%3};" \
        : "+f"((d)[0]), "+f"((d)[1]), "+f"((d)[2]), "+f"((d)[3]) \
        : "r"((a)[0]), "r"((a)[1]), "r"((a)[2]), "r"((a)[3]), "r"(b0v), "r"(b1v))

#define CP_ASYNC16(dst, src) \
    asm volatile("cp.async.cg.shared.global [%0], [%1], 16;" :: "r"(dst), "l"(src) : "memory")
#define CP_COMMIT() asm volatile("cp.async.commit_group;" ::: "memory")
#define CP_WAIT0()  asm volatile("cp.async.wait_group 0;" ::: "memory")
#define CP_WAIT1()  asm volatile("cp.async.wait_group 1;" ::: "memory")

// ---- smem layouts ----
// aggr: A_HI 0, A_LO 16384; B stages at 32768 + s*32768 (hi +0, lo +16384)
#define AG_BST(s)  (32768 + (s) * 32768)
#define AG_SRS     98304
#define AG_SRINV   98816
#define AG_TOT     99328
// gemm1h: A_HI 0, A_LO 16384, B_HI 32768, B_LO 49152
#define SG_SUM  65536
#define SG_SQ   66048
#define SG_TOT  66560
// gemm2h
#define S2_AFF  65536
#define S2_SUM  67584
#define S2_SQ   68096
#define S2_TOT  68608

extern __shared__ __align__(1024) char dsm[];

// ---------------------------------------------------------------------------
// Shared consumer: one K=64 chunk, 3-pass bf16-split HMMA into acc[2][8][4].
// aBase = sb + a_row*128 (A_HI at +0, A_LO at +16384)
// bBase = sb + <stage hi base> + (wc*64 + b_nin)*128 (LO at +16384)
// ---------------------------------------------------------------------------
__device__ __forceinline__ void consume64(uint32_t aBase, uint32_t bBase,
                                          int a_kb, uint32_t a_xm,
                                          int b_kb, uint32_t b_xm,
                                          float (&acc)[2][8][4]) {
    #pragma unroll
    for (int ks = 0; ks < 4; ks++) {
        const uint32_t kA = ((uint32_t)(ks * 32 + a_kb)) ^ a_xm;
        uint32_t ah[2][4], al[2][4];
        LDMX4(ah[0], aBase + kA);
        LDMX4(ah[1], aBase + 2048 + kA);
        LDMX4(al[0], aBase + 16384 + kA);
        LDMX4(al[1], aBase + 16384 + 2048 + kA);

        const uint32_t kB = ((uint32_t)(ks * 32 + b_kb)) ^ b_xm;
        #pragma unroll
        for (int nh = 0; nh < 2; nh++) {
            uint32_t bh[2][4], bl[2][4];
            LDMX4(bh[0], bBase + (uint32_t)(nh * 4096) + kB);
            LDMX4(bh[1], bBase + (uint32_t)(nh * 4096 + 2048) + kB);
            LDMX4(bl[0], bBase + 16384u + (uint32_t)(nh * 4096) + kB);
            LDMX4(bl[1], bBase + 16384u + (uint32_t)(nh * 4096 + 2048) + kB);
            #pragma unroll
            for (int nf4 = 0; nf4 < 4; nf4++) {
                const int qq = nf4 >> 1, hh = (nf4 & 1) * 2;
                const int nf = nh * 4 + nf4;
                #pragma unroll
                for (int mf = 0; mf < 2; mf++) {
                    MMA_BF16(acc[mf][nf], ah[mf], bh[qq][hh], bh[qq][hh + 1]);
                    MMA_BF16(acc[mf][nf], ah[mf], bl[qq][hh], bl[qq][hh + 1]);
                    MMA_BF16(acc[mf][nf], al[mf], bh[qq][hh], bh[qq][hh + 1]);
                }
            }
        }
    }
}

// ---------------------------------------------------------------------------
// K0: zero stats accumulators
// ---------------------------------------------------------------------------
__global__ void k_zero() {
    int t = threadIdx.x;
    if (t < 768) g_stats[t] = 0.f;
}

// ---------------------------------------------------------------------------
// Kp: transpose P -> Pt_hi / Pt_lo (bf16 split), [b][d][j]
// ---------------------------------------------------------------------------
__global__ __launch_bounds__(256) void k_prep(const float* __restrict__ P) {
    __shared__ float s[32][33];
    int b = blockIdx.z, j0 = blockIdx.x * 32, d0 = blockIdx.y * 32;
    int t = threadIdx.x;
    {
        int jr = t >> 3, dq = (t & 7) * 4;
        float4 v = *(const float4*)(P + ((long)b * NN + j0 + jr) * DD + d0 + dq);
        s[jr][dq + 0] = v.x; s[jr][dq + 1] = v.y; s[jr][dq + 2] = v.z; s[jr][dq + 3] = v.w;
    }
    __syncthreads();
    int d = t >> 3, jq = (t & 7) * 4;
    float x0 = s[jq + 0][d], x1 = s[jq + 1][d], x2 = s[jq + 2][d], x3 = s[jq + 3][d];
    uint32_t h01 = prmt_hi(__float_as_uint(x0), __float_as_uint(x1));
    uint32_t h23 = prmt_hi(__float_as_uint(x2), __float_as_uint(x3));
    uint32_t l01 = cvt_bf16x2(x0 - trunc_bf(x0), x1 - trunc_bf(x1));
    uint32_t l23 = cvt_bf16x2(x2 - trunc_bf(x2), x3 - trunc_bf(x3));
    long off = ((long)b * DD + d0 + d) * NN + j0 + jq;
    *(uint2*)(g_pt_hi + off) = make_uint2(h01, h23);
    *(uint2*)(g_pt_lo + off) = make_uint2(l01, l23);
}

// ---------------------------------------------------------------------------
// Kw: split W1 / W2 into bf16 hi/lo
// ---------------------------------------------------------------------------
__global__ __launch_bounds__(256) void k_wsplit(const float* __restrict__ W1,
                                                const float* __restrict__ W2) {
    int i = blockIdx.x * 256 + threadIdx.x;
    if (i < C1 * C1) {
        float f = W1[i];
        ((unsigned short*)g_w1h)[i] = (unsigned short)(__float_as_uint(f) >> 16);
        g_w1l[i] = __float2bfloat16(f - trunc_bf(f));
    } else if (i < C1 * C1 + C2 * C1) {
        int j = i - C1 * C1;
        float f = W2[j];
        ((unsigned short*)g_w2h)[j] = (unsigned short)(__float_as_uint(f) >> 16);
        g_w2l[j] = __float2bfloat16(f - trunc_bf(f));
    }
}

// ---------------------------------------------------------------------------
// K1: pipelined bf16-split HMMA aggr.
//  - E: coalesced LDG (unit-linear), half-chunk register prefetch
//  - B (Pt): cp.async, double-buffered stages
// ---------------------------------------------------------------------------
__global__ __launch_bounds__(256, 2) void k_aggr(const float* __restrict__ Ed,
                                                 const float* __restrict__ Ei) {
    const uint32_t sb = smem_u32(dsm);
    const int tid = threadIdx.x;
    const int lane = tid & 31, wid = tid >> 5;
    const int wr = wid >> 1, wc = wid & 1;
    const int b = blockIdx.y, i0 = blockIdx.x * 128, edge = blockIdx.z;
    const float* Ebase = (edge ? Ei : Ed) + ((long)b * NN + i0) * NN;
    const __nv_bfloat16* Bh_g = g_pt_hi + (long)b * DD * NN;
    const __nv_bfloat16* Bl_g = g_pt_lo + (long)b * DD * NN;

    // consumer lane addressing
    const int a_rin = (lane & 7) + ((lane >> 3) & 1) * 8;
    const int a_kb  = ((lane >> 3) >> 1) * 16;
    const int a_row = wr * 32 + a_rin;
    const uint32_t a_xm = (uint32_t)((a_row & 7) << 4);
    const uint32_t aBase = sb + (uint32_t)(a_row * 128);

    const int b_nin = (lane & 7) + (lane >= 16 ? 8 : 0);
    const int b_kb  = ((lane >> 3) & 1) * 16;
    const uint32_t b_xm = (uint32_t)(((b_nin & 7)) << 4);
    const uint32_t bRow = (uint32_t)((wc * 64 + b_nin) * 128);

    float acc[2][8][4];
    #pragma unroll
    for (int mf = 0; mf < 2; mf++)
        #pragma unroll
        for (int nf = 0; nf < 8; nf++)
            #pragma unroll
            for (int q = 0; q < 4; q++) acc[mf][nf][q] = 0.f;

    float rs[8];
    #pragma unroll
    for (int i = 0; i < 8; i++) rs[i] = 0.f;

    float4 v[4];

    // B stage fill via cp.async (one chunk = 128 d-rows x 64 k bf16, hi+lo)
    #define AGGR_CPB(c) do { \
        int _k0 = (c) * 64; \
        uint32_t _st = sb + AG_BST((c) & 1); \
        _Pragma("unroll") \
        for (int _it = 0; _it < 4; _it++) { \
            int _idx = tid + _it * 256; \
            int _d = _idx >> 3, _u = _idx & 7; \
            uint32_t _dst = _st + (uint32_t)(_d * 128) + (uint32_t)((_u * 16) ^ ((_d & 7) << 4)); \
            CP_ASYNC16(_dst,          Bh_g + (long)_d * NN + _k0 + _u * 8); \
            CP_ASYNC16(_dst + 16384u, Bl_g + (long)_d * NN + _k0 + _u * 8); \
        } \
        CP_COMMIT(); \
    } while (0)

    #define AGGR_LOADE(c, h) do { \
        int _k0 = (c) * 64; \
        _Pragma("unroll") \
        for (int _it = 0; _it < 4; _it++) { \
            int _idx = tid + ((h) * 4 + _it) * 256; \
            int _row = _idx >> 4, _cu = _idx & 15; \
            v[_it] = *(const float4*)(Ebase + (long)_row * NN + _k0 + _cu * 4); \
        } \
    } while (0)

    #define AGGR_STOREE(c, h) do { \
        int _k0 = (c) * 64; \
        _Pragma("unroll") \
        for (int _it = 0; _it < 4; _it++) { \
            int _idx = tid + ((h) * 4 + _it) * 256; \
            int _row = _idx >> 4, _cu = _idx & 15; \
            int _irow = i0 + _row, _jb = _k0 + _cu * 4; \
            float4 _a = v[_it]; \
            if (_jb + 0 == _irow) _a.x = 0.f; \
            if (_jb + 1 == _irow) _a.y = 0.f; \
            if (_jb + 2 == _irow) _a.z = 0.f; \
            if (_jb + 3 == _irow) _a.w = 0.f; \
            rs[(h) * 4 + _it] += _a.x + _a.y + _a.z + _a.w; \
            uint32_t _h0 = prmt_hi(__float_as_uint(_a.x), __float_as_uint(_a.y)); \
            uint32_t _h1 = prmt_hi(__float_as_uint(_a.z), __float_as_uint(_a.w)); \
            uint32_t _l0 = cvt_bf16x2(_a.x - trunc_bf(_a.x), _a.y - trunc_bf(_a.y)); \
            uint32_t _l1 = cvt_bf16x2(_a.z - trunc_bf(_a.z), _a.w - trunc_bf(_a.w)); \
            uint32_t _off = (uint32_t)(_row * 128) + \
                (uint32_t)((((_cu >> 1) * 16) ^ ((_row & 7) << 4)) + (_cu & 1) * 8); \
            *(uint2*)(dsm + _off)          = make_uint2(_h0, _h1); \
            *(uint2*)(dsm + 16384 + _off)  = make_uint2(_l0, _l1); \
        } \
    } while (0)

    // prologue
    AGGR_CPB(0);
    AGGR_LOADE(0, 0);

    for (int c = 0; c < 8; c++) {
        if (c < 7) AGGR_CPB(c + 1);
        AGGR_STOREE(c, 0);
        AGGR_LOADE(c, 1);
        AGGR_STOREE(c, 1);
        if (c < 7) { CP_WAIT1(); } else { CP_WAIT0(); }
        __syncthreads();
        if (c < 7) AGGR_LOADE(c + 1, 0);   // overlaps consume
        consume64(aBase, sb + AG_BST(c & 1) + bRow, a_kb, a_xm, b_kb, b_xm, acc);
        __syncthreads();
    }

    // rowsum reduce (16 lanes share a row slot) -> srs
    float* srs = (float*)(dsm + AG_SRS);
    #pragma unroll
    for (int sl = 0; sl < 8; sl++) {
        float s = rs[sl];
        #pragma unroll
        for (int m = 1; m <= 8; m <<= 1) s += __shfl_xor_sync(0xffffffffu, s, m);
        if ((lane & 15) == 0) srs[(tid >> 4) + sl * 16] = s;
    }
    __syncthreads();
    float* rinv = (float*)(dsm + AG_SRINV);
    if (tid < 128) rinv[tid] = 1.f / fmaxf(srs[tid], 1e-12f);
    __syncthreads();

    // epilogue: scale + split bf16 store
    #pragma unroll
    for (int mf = 0; mf < 2; mf++) {
        const int lr0 = wr * 32 + mf * 16 + (lane >> 2);
        const float inv0 = rinv[lr0], inv1 = rinv[lr0 + 8];
        long idx0 = ((long)(b * NN + i0 + lr0)) * C1 + edge * 128 + wc * 64 + 2 * (lane & 3);
        long idx1 = idx0 + 8L * C1;
        #pragma unroll
        for (int nf = 0; nf < 8; nf++) {
            float x0 = acc[mf][nf][0] * inv0, x1 = acc[mf][nf][1] * inv0;
            float y0 = acc[mf][nf][2] * inv1, y1 = acc[mf][nf][3] * inv1;
            *(uint32_t*)(g_xh + idx0 + nf * 8) = prmt_hi(__float_as_uint(x0), __float_as_uint(x1));
            *(uint32_t*)(g_xl + idx0 + nf * 8) = cvt_bf16x2(x0 - trunc_bf(x0), x1 - trunc_bf(x1));
            *(uint32_t*)(g_xh + idx1 + nf * 8) = prmt_hi(__float_as_uint(y0), __float_as_uint(y1));
            *(uint32_t*)(g_xl + idx1 + nf * 8) = cvt_bf16x2(y0 - trunc_bf(y0), y1 - trunc_bf(y1));
        }
    }
}

// ---------------------------------------------------------------------------
// K2: HMMA gemm1: h1 = xcat @ W1^T (+BN stats).  All tiles via cp.async.
// ---------------------------------------------------------------------------
__global__ __launch_bounds__(256, 2) void k_gemm1h() {
    const uint32_t sb = smem_u32(dsm);
    const int tid = threadIdx.x;
    const int lane = tid & 31, wid = tid >> 5;
    const int wr = wid >> 1, wc = wid & 1;
    const long m0 = (long)blockIdx.y * 128;
    const int n0 = blockIdx.x * 128;

    const int a_rin = (lane & 7) + ((lane >> 3) & 1) * 8;
    const int a_kb  = ((lane >> 3) >> 1) * 16;
    const int a_row = wr * 32 + a_rin;
    const uint32_t a_xm = (uint32_t)((a_row & 7) << 4);
    const uint32_t aBase = sb + (uint32_t)(a_row * 128);

    const int b_nin = (lane & 7) + (lane >= 16 ? 8 : 0);
    const int b_kb  = ((lane >> 3) & 1) * 16;
    const uint32_t b_xm = (uint32_t)(((b_nin & 7)) << 4);
    const uint32_t bBase = sb + 32768u + (uint32_t)((wc * 64 + b_nin) * 128);

    float* ssum = (float*)(dsm + SG_SUM);
    float* ssq  = (float*)(dsm + SG_SQ);
    if (tid < 128) { ssum[tid] = 0.f; ssq[tid] = 0.f; }

    float acc[2][8][4];
    #pragma unroll
    for (int mf = 0; mf < 2; mf++)
        #pragma unroll
        for (int nf = 0; nf < 8; nf++)
            #pragma unroll
            for (int q = 0; q < 4; q++) acc[mf][nf][q] = 0.f;

    #define G1_ISSUE(c) do { \
        int _k0 = (c) * 64; \
        _Pragma("unroll") \
        for (int _it = 0; _it < 4; _it++) { \
            int _idx = tid + _it * 256; \
            int _r = _idx >> 3, _u = _idx & 7; \
            uint32_t _dst = sb + (uint32_t)(_r * 128) + (uint32_t)((_u * 16) ^ ((_r & 7) << 4)); \
            CP_ASYNC16(_dst,           g_xh + (m0 + _r) * C1 + _k0 + _u * 8); \
            CP_ASYNC16(_dst + 16384u,  g_xl + (m0 + _r) * C1 + _k0 + _u * 8); \
            CP_ASYNC16(_dst + 32768u,  g_w1h + (long)(n0 + _r) * C1 + _k0 + _u * 8); \
            CP_ASYNC16(_dst + 49152u,  g_w1l + (long)(n0 + _r) * C1 + _k0 + _u * 8); \
        } \
        CP_COMMIT(); \
    } while (0)

    G1_ISSUE(0);
    for (int c = 0; c < 4; c++) {
        CP_WAIT0();
        __syncthreads();
        consume64(aBase, bBase, a_kb, a_xm, b_kb, b_xm, acc);
        __syncthreads();
        if (c < 3) G1_ISSUE(c + 1);
    }

    // store h1 + stats
    #pragma unroll
    for (int mf = 0; mf < 2; mf++) {
        const int lr0 = wr * 32 + mf * 16 + (lane >> 2);
        float* d0 = g_h1 + (m0 + lr0) * C1 + n0 + wc * 64 + 2 * (lane & 3);
        float* d1 = d0 + 8L * C1;
        #pragma unroll
        for (int nf = 0; nf < 8; nf++) {
            *(float2*)(d0 + nf * 8) = make_float2(acc[mf][nf][0], acc[mf][nf][1]);
            *(float2*)(d1 + nf * 8) = make_float2(acc[mf][nf][2], acc[mf][nf][3]);
        }
    }
    #pragma unroll
    for (int nf = 0; nf < 8; nf++) {
        #pragma unroll
        for (int par = 0; par < 2; par++) {
            float v0 = acc[0][nf][par], v1 = acc[0][nf][par + 2];
            float v2 = acc[1][nf][par], v3 = acc[1][nf][par + 2];
            float s = v0 + v1 + v2 + v3;
            float q = v0 * v0 + v1 * v1 + v2 * v2 + v3 * v3;
            #pragma unroll
            for (int m = 4; m <= 16; m <<= 1) {
                s += __shfl_xor_sync(0xffffffffu, s, m);
                q += __shfl_xor_sync(0xffffffffu, q, m);
            }
            if (lane < 4) {
                int ch = wc * 64 + nf * 8 + 2 * lane + par;
                atomicAdd(&ssum[ch], s);
                atomicAdd(&ssq[ch], q);
            }
        }
    }
    __syncthreads();
    if (tid < 128) {
        atomicAdd(&g_stats[n0 + tid], ssum[tid]);
        atomicAdd(&g_stats[256 + n0 + tid], ssq[tid]);
    }
}

// ---------------------------------------------------------------------------
// K3/K5: stats -> (scale, shift)
// ---------------------------------------------------------------------------
__global__ void k_bnaff(const float* __restrict__ g, const float* __restrict__ b,
                        int C, int statoff, int affoff) {
    int o = threadIdx.x;
    if (o < C) {
        const float inv_cnt = 1.f / 131072.f;
        float mean = g_stats[statoff + o] * inv_cnt;
        float var  = g_stats[statoff + C + o] * inv_cnt - mean * mean;
        float sc = g[o] * rsqrtf(var + 1e-5f);
        g_aff[affoff + o]     = sc;
        g_aff[affoff + C + o] = b[o] - mean * sc;
    }
}

// ---------------------------------------------------------------------------
// K4: HMMA gemm2: h2 = lrelu(affine1(h1)) @ W2^T (+BN2 stats).
//  A: coalesced fp32 load + affine + split; B: cp.async.
// ---------------------------------------------------------------------------
__global__ __launch_bounds__(256, 2) void k_gemm2h() {
    const uint32_t sb = smem_u32(dsm);
    const int tid = threadIdx.x;
    const int lane = tid & 31, wid = tid >> 5;
    const int wr = wid >> 1, wc = wid & 1;
    const long m0 = (long)blockIdx.x * 128;

    const int a_rin = (lane & 7) + ((lane >> 3) & 1) * 8;
    const int a_kb  = ((lane >> 3) >> 1) * 16;
    const int a_row = wr * 32 + a_rin;
    const uint32_t a_xm = (uint32_t)((a_row & 7) << 4);
    const uint32_t aBase = sb + (uint32_t)(a_row * 128);

    const int b_nin = (lane & 7) + (lane >= 16 ? 8 : 0);
    const int b_kb  = ((lane >> 3) & 1) * 16;
    const uint32_t b_xm = (uint32_t)(((b_nin & 7)) << 4);
    const uint32_t bBase = sb + 32768u + (uint32_t)((wc * 64 + b_nin) * 128);

    float* saff0 = (float*)(dsm + S2_AFF);
    float* saff1 = saff0 + 256;
    float* ssum  = (float*)(dsm + S2_SUM);
    float* ssq   = (float*)(dsm + S2_SQ);
    saff0[tid] = g_aff[tid];
    saff1[tid] = g_aff[256 + tid];
    if (tid < 128) { ssum[tid] = 0.f; ssq[tid] = 0.f; }
    __syncthreads();

    float acc[2][8][4];
    #pragma unroll
    for (int mf = 0; mf < 2; mf++)
        #pragma unroll
        for (int nf = 0; nf < 8; nf++)
            #pragma unroll
            for (int q = 0; q < 4; q++) acc[mf][nf][q] = 0.f;

    for (int c = 0; c < 4; c++) {
        const int k0 = c * 64;
        // B via cp.async
        #pragma unroll
        for (int it = 0; it < 4; it++) {
            int idx = tid + it * 256;
            int r = idx >> 3, u = idx & 7;
            uint32_t dst = sb + 32768u + (uint32_t)(r * 128) + (uint32_t)((u * 16) ^ ((r & 7) << 4));
            CP_ASYNC16(dst,          g_w2h + (long)r * C1 + k0 + u * 8);
            CP_ASYNC16(dst + 16384u, g_w2l + (long)r * C1 + k0 + u * 8);
        }
        CP_COMMIT();
        // A: coalesced fp32 + affine + split
        #pragma unroll
        for (int it = 0; it < 8; it++) {
            int idx = tid + it * 256;
            int row = idx >> 4, cu = idx & 15;
            float4 a = *(const float4*)(g_h1 + (m0 + row) * C1 + k0 + cu * 4);
            int ch = k0 + cu * 4;
            a.x = lrelu(saff0[ch + 0] * a.x + saff1[ch + 0]);
            a.y = lrelu(saff0[ch + 1] * a.y + saff1[ch + 1]);
            a.z = lrelu(saff0[ch + 2] * a.z + saff1[ch + 2]);
            a.w = lrelu(saff0[ch + 3] * a.w + saff1[ch + 3]);
            uint32_t h0 = prmt_hi(__float_as_uint(a.x), __float_as_uint(a.y));
            uint32_t h1v = prmt_hi(__float_as_uint(a.z), __float_as_uint(a.w));
            uint32_t l0 = cvt_bf16x2(a.x - trunc_bf(a.x), a.y - trunc_bf(a.y));
            uint32_t l1 = cvt_bf16x2(a.z - trunc_bf(a.z), a.w - trunc_bf(a.w));
            uint32_t off = (uint32_t)(row * 128) +
                (uint32_t)((((cu >> 1) * 16) ^ ((row & 7) << 4)) + (cu & 1) * 8);
            *(uint2*)(dsm + off)         = make_uint2(h0, h1v);
            *(uint2*)(dsm + 16384 + off) = make_uint2(l0, l1);
        }
        CP_WAIT0();
        __syncthreads();
        consume64(aBase, bBase, a_kb, a_xm, b_kb, b_xm, acc);
        __syncthreads();
    }

    // store h2 + stats
    #pragma unroll
    for (int mf = 0; mf < 2; mf++) {
        const int lr0 = wr * 32 + mf * 16 + (lane >> 2);
        float* d0 = g_h2 + (m0 + lr0) * C2 + wc * 64 + 2 * (lane & 3);
        float* d1 = d0 + 8L * C2;
        #pragma unroll
        for (int nf = 0; nf < 8; nf++) {
            *(float2*)(d0 + nf * 8) = make_float2(acc[mf][nf][0], acc[mf][nf][1]);
            *(float2*)(d1 + nf * 8) = make_float2(acc[mf][nf][2], acc[mf][nf][3]);
        }
    }
    #pragma unroll
    for (int nf = 0; nf < 8; nf++) {
        #pragma unroll
        for (int par = 0; par < 2; par++) {
            float v0 = acc[0][nf][par], v1 = acc[0][nf][par + 2];
            float v2 = acc[1][nf][par], v3 = acc[1][nf][par + 2];
            float s = v0 + v1 + v2 + v3;
            float q = v0 * v0 + v1 * v1 + v2 * v2 + v3 * v3;
            #pragma unroll
            for (int m = 4; m <= 16; m <<= 1) {
                s += __shfl_xor_sync(0xffffffffu, s, m);
                q += __shfl_xor_sync(0xffffffffu, q, m);
            }
            if (lane < 4) {
                int ch = wc * 64 + nf * 8 + 2 * lane + par;
                atomicAdd(&ssum[ch], s);
                atomicAdd(&ssq[ch], q);
            }
        }
    }
    __syncthreads();
    if (tid < 128) {
        atomicAdd(&g_stats[512 + tid], ssum[tid]);
        atomicAdd(&g_stats[640 + tid], ssq[tid]);
    }
}

// ---------------------------------------------------------------------------
// K6: out = lrelu(scale2*h2 + shift2)
// ---------------------------------------------------------------------------
__global__ __launch_bounds__(256) void k_final(float* __restrict__ out) {
    long idx = ((long)blockIdx.x * blockDim.x + threadIdx.x);
    long e = idx * 4;
    int ch = (int)(e & 127);
    float4 v = *(const float4*)&g_h2[e];
    v.x = lrelu(g_aff[512 + ch + 0] * v.x + g_aff[640 + ch + 0]);
    v.y = lrelu(g_aff[512 + ch + 1] * v.y + g_aff[640 + ch + 1]);
    v.z = lrelu(g_aff[512 + ch + 2] * v.z + g_aff[640 + ch + 2]);
    v.w = lrelu(g_aff[512 + ch + 3] * v.w + g_aff[640 + ch + 3]);
    *(float4*)&out[e] = v;
}

// ---------------------------------------------------------------------------
extern "C" void kernel_launch(void* const* d_in, const int* in_sizes, int n_in,
                              void* d_out, int out_size) {
    const float* Ed = (const float*)d_in[0];
    const float* Ei = (const float*)d_in[1];
    const float* P  = (const float*)d_in[2];
    const float* g1 = (const float*)d_in[4];
    const float* b1 = (const float*)d_in[5];
    const float* W1 = (const float*)d_in[3];
    const float* W2 = (const float*)d_in[6];
    const float* g2 = (const float*)d_in[7];
    const float* b2 = (const float*)d_in[8];
    float* out = (float*)d_out;

    cudaFuncSetAttribute((const void*)k_aggr,
                         cudaFuncAttributeMaxDynamicSharedMemorySize, AG_TOT);
    cudaFuncSetAttribute((const void*)k_gemm1h,
                         cudaFuncAttributeMaxDynamicSharedMemorySize, SG_TOT);
    cudaFuncSetAttribute((const void*)k_gemm2h,
                         cudaFuncAttributeMaxDynamicSharedMemorySize, S2_TOT);

    k_zero<<<1, 768>>>();
    k_prep<<<dim3(16, 4, 256), 256>>>(P);
    k_wsplit<<<384, 256>>>(W1, W2);
    k_aggr<<<dim3(4, 256, 2), 256, AG_TOT>>>(Ed, Ei);
    k_gemm1h<<<dim3(2, 1024), 256, SG_TOT>>>();
    k_bnaff<<<1, 256>>>(g1, b1, 256, 0, 0);
    k_gemm2h<<<1024, 256, S2_TOT>>>();
    k_bnaff<<<1, 128>>>(g2, b2, 128, 512, 512);
    k_final<<<(int)(BN_ * C2 / 4 / 256), 256>>>(out);
}

// round 10
// speedup vs baseline: 2.0778x; 1.0967x over previous
#include <cuda_runtime.h>
#include <cuda_bf16.h>
#include <cstdint>

// Problem constants
#define BB   256
#define NN   512
#define DD   128
#define C1   256          // 2*D
#define C2   128
#define BN_  131072L      // BB*NN

// Scratch (device globals; no cudaMalloc allowed)
__device__ float g_h1[BN_ * C1];
__device__ float g_h2[BN_ * C2];
__device__ float g_stats[768];
__device__ float g_aff[768];
__device__ __nv_bfloat16 g_pt_hi[(long)BB * DD * NN];   // P^T hi, [b][d][j]
__device__ __nv_bfloat16 g_pt_lo[(long)BB * DD * NN];   // P^T lo
__device__ __nv_bfloat16 g_xh[BN_ * C1];                // xcat hi (bf16 split)
__device__ __nv_bfloat16 g_xl[BN_ * C1];                // xcat lo
__device__ __nv_bfloat16 g_w1h[C1 * C1];
__device__ __nv_bfloat16 g_w1l[C1 * C1];
__device__ __nv_bfloat16 g_w2h[C2 * C1];
__device__ __nv_bfloat16 g_w2l[C2 * C1];

__device__ __forceinline__ float lrelu(float v) { return v >= 0.f ? v : 0.01f * v; }

__device__ __forceinline__ uint32_t smem_u32(const void* p) {
    uint32_t a;
    asm("{ .reg .u64 t; cvta.to.shared.u64 t, %1; cvt.u32.u64 %0, t; }" : "=r"(a) : "l"(p));
    return a;
}

__device__ __forceinline__ uint32_t prmt_hi(uint32_t a, uint32_t b) {
    uint32_t r; asm("prmt.b32 %0, %1, %2, 0x7632;" : "=r"(r) : "r"(a), "r"(b)); return r;
}
__device__ __forceinline__ uint32_t cvt_bf16x2(float x, float y) {
    uint32_t r; asm("cvt.rn.bf16x2.f32 %0, %1, %2;" : "=r"(r) : "f"(y), "f"(x)); return r;
}
__device__ __forceinline__ float trunc_bf(float x) {
    return __uint_as_float(__float_as_uint(x) & 0xFFFF0000u);
}

#define LDMX4(r, addr) \
    asm volatile("ldmatrix.sync.aligned.m8n8.x4.shared.b16 {%0,%1,%2,%3}, [%4];" \
        : "=r"((r)[0]), "=r"((r)[1]), "=r"((r)[2]), "=r"((r)[3]) : "r"(addr))

#define MMA_BF16(d, a, b0v, b1v) \
    asm volatile("mma.sync.aligned.m16n8k16.row.col.f32.bf16.bf16.f32 " \
        "{%0,%1,%2,%3}, {%4,%5,%6,%7}, {%8,%9}, {%0,%1,%2,%3};" \
        : "+f"((d)[0]), "+f"((d)[1]), "+f"((d)[2]), "+f"((d)[3]) \
        : "r"((a)[0]), "r"((a)[1]), "r"((a)[2]), "r"((a)[3]), "r"(b0v), "r"(b1v))

#define CP_ASYNC16(dst, src) \
    asm volatile("cp.async.cg.shared.global [%0], [%1], 16;" :: "r"(dst), "l"(src) : "memory")
#define CP_COMMIT() asm volatile("cp.async.commit_group;" ::: "memory")
#define CP_WAIT0()  asm volatile("cp.async.wait_group 0;" ::: "memory")
#define CP_WAIT1()  asm volatile("cp.async.wait_group 1;" ::: "memory")

// 64-byte-row tile swizzle: xor bits[4:6) with row bits[1:3)
#define SW64R(row, off) ((uint32_t)(off) ^ ((((uint32_t)(row) >> 1) & 3u) << 4))

// ---- smem layouts (K=32 tiles: 128 rows x 64 B; hi at +0, lo at +8192) ----
// aggr: A stages 0,16384; B stages 32768 + s*16384 (s<3)
#define AG_SRS     81920
#define AG_SRINV   82432
#define AG_TOT     82944
// gemm1h: stages s*32768 (s<3): A_HI+0, A_LO+8192, B_HI+16384, B_LO+24576
#define SG_SUM  98304
#define SG_SQ   98816
#define SG_TOT  99328
// gemm2h: A 0,16384; B 32768+s*16384 (s<3)
#define S2_AFF  81920
#define S2_SUM  83968
#define S2_SQ   84480
#define S2_TOT  84992

extern __shared__ __align__(1024) char dsm[];

// ---------------------------------------------------------------------------
// consume32: one K=32 chunk, 3-pass bf16-split HMMA into acc[2][8][4].
// aHi = sb + Astage + a_row*64 ; lo at +8192 ; mf=1 at +1024
// bHi = sb + Bstage + (wc*64+b_nin)*64 ; lo +8192 ; nh*2048 ; +1024 per n16
// ---------------------------------------------------------------------------
__device__ __forceinline__ void consume32(uint32_t aHi, uint32_t bHi,
                                          int a_kb, uint32_t a_xm,
                                          int b_kb, uint32_t b_xm,
                                          float (&acc)[2][8][4]) {
    #pragma unroll
    for (int ks = 0; ks < 2; ks++) {
        const uint32_t kA = ((uint32_t)(ks * 32 + a_kb)) ^ a_xm;
        uint32_t ah[2][4], al[2][4];
        LDMX4(ah[0], aHi + kA);
        LDMX4(ah[1], aHi + 1024 + kA);
        LDMX4(al[0], aHi + 8192 + kA);
        LDMX4(al[1], aHi + 8192 + 1024 + kA);

        const uint32_t kB = ((uint32_t)(ks * 32 + b_kb)) ^ b_xm;
        #pragma unroll
        for (int nh = 0; nh < 2; nh++) {
            uint32_t bh[2][4], bl[2][4];
            LDMX4(bh[0], bHi + (uint32_t)(nh * 2048) + kB);
            LDMX4(bh[1], bHi + (uint32_t)(nh * 2048 + 1024) + kB);
            LDMX4(bl[0], bHi + 8192u + (uint32_t)(nh * 2048) + kB);
            LDMX4(bl[1], bHi + 8192u + (uint32_t)(nh * 2048 + 1024) + kB);
            #pragma unroll
            for (int nf4 = 0; nf4 < 4; nf4++) {
                const int qq = nf4 >> 1, hh = (nf4 & 1) * 2;
                const int nf = nh * 4 + nf4;
                #pragma unroll
                for (int mf = 0; mf < 2; mf++) {
                    MMA_BF16(acc[mf][nf], ah[mf], bh[qq][hh], bh[qq][hh + 1]);
                    MMA_BF16(acc[mf][nf], ah[mf], bl[qq][hh], bl[qq][hh + 1]);
                    MMA_BF16(acc[mf][nf], al[mf], bh[qq][hh], bh[qq][hh + 1]);
                }
            }
        }
    }
}

// ---------------------------------------------------------------------------
__global__ void k_zero() {
    int t = threadIdx.x;
    if (t < 768) g_stats[t] = 0.f;
}

// ---------------------------------------------------------------------------
__global__ __launch_bounds__(256) void k_prep(const float* __restrict__ P) {
    __shared__ float s[32][33];
    int b = blockIdx.z, j0 = blockIdx.x * 32, d0 = blockIdx.y * 32;
    int t = threadIdx.x;
    {
        int jr = t >> 3, dq = (t & 7) * 4;
        float4 v = *(const float4*)(P + ((long)b * NN + j0 + jr) * DD + d0 + dq);
        s[jr][dq + 0] = v.x; s[jr][dq + 1] = v.y; s[jr][dq + 2] = v.z; s[jr][dq + 3] = v.w;
    }
    __syncthreads();
    int d = t >> 3, jq = (t & 7) * 4;
    float x0 = s[jq + 0][d], x1 = s[jq + 1][d], x2 = s[jq + 2][d], x3 = s[jq + 3][d];
    uint32_t h01 = prmt_hi(__float_as_uint(x0), __float_as_uint(x1));
    uint32_t h23 = prmt_hi(__float_as_uint(x2), __float_as_uint(x3));
    uint32_t l01 = cvt_bf16x2(x0 - trunc_bf(x0), x1 - trunc_bf(x1));
    uint32_t l23 = cvt_bf16x2(x2 - trunc_bf(x2), x3 - trunc_bf(x3));
    long off = ((long)b * DD + d0 + d) * NN + j0 + jq;
    *(uint2*)(g_pt_hi + off) = make_uint2(h01, h23);
    *(uint2*)(g_pt_lo + off) = make_uint2(l01, l23);
}

// ---------------------------------------------------------------------------
__global__ __launch_bounds__(256) void k_wsplit(const float* __restrict__ W1,
                                                const float* __restrict__ W2) {
    int i = blockIdx.x * 256 + threadIdx.x;
    if (i < C1 * C1) {
        float f = W1[i];
        ((unsigned short*)g_w1h)[i] = (unsigned short)(__float_as_uint(f) >> 16);
        g_w1l[i] = __float2bfloat16(f - trunc_bf(f));
    } else if (i < C1 * C1 + C2 * C1) {
        int j = i - C1 * C1;
        float f = W2[j];
        ((unsigned short*)g_w2h)[j] = (unsigned short)(__float_as_uint(f) >> 16);
        g_w2l[j] = __float2bfloat16(f - trunc_bf(f));
    }
}

// ---------------------------------------------------------------------------
// K1: deep-pipelined bf16-split HMMA aggr. K=32 chunks x16.
//  A: 2-stage (LDG+convert under tensor shadow); B: 3-stage cp.async.
// ---------------------------------------------------------------------------
__global__ __launch_bounds__(256, 2) void k_aggr(const float* __restrict__ Ed,
                                                 const float* __restrict__ Ei) {
    const uint32_t sb = smem_u32(dsm);
    const int tid = threadIdx.x;
    const int lane = tid & 31, wid = tid >> 5;
    const int wr = wid >> 1, wc = wid & 1;
    const int b = blockIdx.y, i0 = blockIdx.x * 128, edge = blockIdx.z;
    const float* Ebase = (edge ? Ei : Ed) + ((long)b * NN + i0) * NN;
    const __nv_bfloat16* Bh_g = g_pt_hi + (long)b * DD * NN;
    const __nv_bfloat16* Bl_g = g_pt_lo + (long)b * DD * NN;

    // consumer lane addressing
    const int a_rin = (lane & 7) + ((lane >> 3) & 1) * 8;
    const int a_kb  = (lane >> 4) * 16;
    const int a_row = wr * 32 + a_rin;
    const uint32_t a_xm = (((uint32_t)a_rin >> 1) & 3u) << 4;
    const uint32_t aRow = (uint32_t)(a_row * 64);

    const int b_nin = (lane & 7) + (lane >= 16 ? 8 : 0);
    const int b_kb  = ((lane >> 3) & 1) * 16;
    const uint32_t b_xm = (((uint32_t)b_nin >> 1) & 3u) << 4;
    const uint32_t bRow = (uint32_t)((wc * 64 + b_nin) * 64);

    float acc[2][8][4];
    #pragma unroll
    for (int mf = 0; mf < 2; mf++)
        #pragma unroll
        for (int nf = 0; nf < 8; nf++)
            #pragma unroll
            for (int q = 0; q < 4; q++) acc[mf][nf][q] = 0.f;

    float rs[4];
    #pragma unroll
    for (int i = 0; i < 4; i++) rs[i] = 0.f;

    float4 v[4];

    // B chunk via cp.async: 128 rows x 32 k bf16 (hi+lo), 4 cps/thread
    #define AGGR_CPB(c) do { \
        int _k0 = (c) * 32; \
        uint32_t _st = sb + 32768u + (uint32_t)(((c) % 3) * 16384); \
        _Pragma("unroll") \
        for (int _it = 0; _it < 2; _it++) { \
            int _idx = tid + _it * 256; \
            int _d = _idx >> 2, _u = _idx & 3; \
            uint32_t _dst = _st + (uint32_t)(_d * 64) + SW64R(_d, _u * 16); \
            CP_ASYNC16(_dst,         Bh_g + (long)_d * NN + _k0 + _u * 8); \
            CP_ASYNC16(_dst + 8192u, Bl_g + (long)_d * NN + _k0 + _u * 8); \
        } \
        CP_COMMIT(); \
    } while (0)

    #define AGGR_LOADE(c) do { \
        int _k0 = (c) * 32; \
        _Pragma("unroll") \
        for (int _it = 0; _it < 4; _it++) { \
            int _idx = tid + _it * 256; \
            int _row = _idx >> 3, _cu = _idx & 7; \
            v[_it] = *(const float4*)(Ebase + (long)_row * NN + _k0 + _cu * 4); \
        } \
    } while (0)

    #define AGGR_STOREE(c) do { \
        int _k0 = (c) * 32; \
        uint32_t _st = sb + (uint32_t)(((c) & 1) * 16384); \
        _Pragma("unroll") \
        for (int _it = 0; _it < 4; _it++) { \
            int _idx = tid + _it * 256; \
            int _row = _idx >> 3, _cu = _idx & 7; \
            int _irow = i0 + _row, _jb = _k0 + _cu * 4; \
            float4 _a = v[_it]; \
            if (_jb + 0 == _irow) _a.x = 0.f; \
            if (_jb + 1 == _irow) _a.y = 0.f; \
            if (_jb + 2 == _irow) _a.z = 0.f; \
            if (_jb + 3 == _irow) _a.w = 0.f; \
            rs[_it] += _a.x + _a.y + _a.z + _a.w; \
            uint32_t _h0 = prmt_hi(__float_as_uint(_a.x), __float_as_uint(_a.y)); \
            uint32_t _h1 = prmt_hi(__float_as_uint(_a.z), __float_as_uint(_a.w)); \
            uint32_t _l0 = cvt_bf16x2(_a.x - trunc_bf(_a.x), _a.y - trunc_bf(_a.y)); \
            uint32_t _l1 = cvt_bf16x2(_a.z - trunc_bf(_a.z), _a.w - trunc_bf(_a.w)); \
            uint32_t _off = _st - sb + (uint32_t)(_row * 64) + \
                            SW64R(_row, (_cu >> 1) * 16) + (uint32_t)((_cu & 1) * 8); \
            *(uint2*)(dsm + _off)        = make_uint2(_h0, _h1); \
            *(uint2*)(dsm + 8192 + _off) = make_uint2(_l0, _l1); \
        } \
    } while (0)

    // prologue
    AGGR_CPB(0);
    AGGR_CPB(1);
    AGGR_LOADE(0);
    AGGR_STOREE(0);
    AGGR_LOADE(1);

    for (int c = 0; c < 16; c++) {
        if (c == 15) { CP_WAIT0(); } else { CP_WAIT1(); }
        __syncthreads();
        if (c < 14) AGGR_CPB(c + 2);
        uint32_t aHi = sb + (uint32_t)((c & 1) * 16384) + aRow;
        uint32_t bHi = sb + 32768u + (uint32_t)((c % 3) * 16384) + bRow;
        consume32(aHi, bHi, a_kb, a_xm, b_kb, b_xm, acc);
        if (c < 15) AGGR_STOREE(c + 1);
        if (c < 14) AGGR_LOADE(c + 2);
    }

    // rowsum reduce: 8 consecutive threads share a row
    __syncthreads();
    float* srs = (float*)(dsm + AG_SRS);
    #pragma unroll
    for (int it = 0; it < 4; it++) {
        float s = rs[it];
        #pragma unroll
        for (int m = 1; m <= 4; m <<= 1) s += __shfl_xor_sync(0xffffffffu, s, m);
        if ((lane & 7) == 0) srs[(tid >> 3) + it * 32] = s;
    }
    __syncthreads();
    float* rinv = (float*)(dsm + AG_SRINV);
    if (tid < 128) rinv[tid] = 1.f / fmaxf(srs[tid], 1e-12f);
    __syncthreads();

    // epilogue: scale + split bf16 store
    #pragma unroll
    for (int mf = 0; mf < 2; mf++) {
        const int lr0 = wr * 32 + mf * 16 + (lane >> 2);
        const float inv0 = rinv[lr0], inv1 = rinv[lr0 + 8];
        long idx0 = ((long)(b * NN + i0 + lr0)) * C1 + edge * 128 + wc * 64 + 2 * (lane & 3);
        long idx1 = idx0 + 8L * C1;
        #pragma unroll
        for (int nf = 0; nf < 8; nf++) {
            float x0 = acc[mf][nf][0] * inv0, x1 = acc[mf][nf][1] * inv0;
            float y0 = acc[mf][nf][2] * inv1, y1 = acc[mf][nf][3] * inv1;
            *(uint32_t*)(g_xh + idx0 + nf * 8) = prmt_hi(__float_as_uint(x0), __float_as_uint(x1));
            *(uint32_t*)(g_xl + idx0 + nf * 8) = cvt_bf16x2(x0 - trunc_bf(x0), x1 - trunc_bf(x1));
            *(uint32_t*)(g_xh + idx1 + nf * 8) = prmt_hi(__float_as_uint(y0), __float_as_uint(y1));
            *(uint32_t*)(g_xl + idx1 + nf * 8) = cvt_bf16x2(y0 - trunc_bf(y0), y1 - trunc_bf(y1));
        }
    }
}

// ---------------------------------------------------------------------------
// K2: HMMA gemm1 (3-stage all-cp.async pipeline, K=32 x8 chunks) + BN stats
// ---------------------------------------------------------------------------
__global__ __launch_bounds__(256, 2) void k_gemm1h() {
    const uint32_t sb = smem_u32(dsm);
    const int tid = threadIdx.x;
    const int lane = tid & 31, wid = tid >> 5;
    const int wr = wid >> 1, wc = wid & 1;
    const long m0 = (long)blockIdx.y * 128;
    const int n0 = blockIdx.x * 128;

    const int a_rin = (lane & 7) + ((lane >> 3) & 1) * 8;
    const int a_kb  = (lane >> 4) * 16;
    const int a_row = wr * 32 + a_rin;
    const uint32_t a_xm = (((uint32_t)a_rin >> 1) & 3u) << 4;
    const uint32_t aRow = (uint32_t)(a_row * 64);

    const int b_nin = (lane & 7) + (lane >= 16 ? 8 : 0);
    const int b_kb  = ((lane >> 3) & 1) * 16;
    const uint32_t b_xm = (((uint32_t)b_nin >> 1) & 3u) << 4;
    const uint32_t bRow = (uint32_t)((wc * 64 + b_nin) * 64);

    float* ssum = (float*)(dsm + SG_SUM);
    float* ssq  = (float*)(dsm + SG_SQ);
    if (tid < 128) { ssum[tid] = 0.f; ssq[tid] = 0.f; }

    float acc[2][8][4];
    #pragma unroll
    for (int mf = 0; mf < 2; mf++)
        #pragma unroll
        for (int nf = 0; nf < 8; nf++)
            #pragma unroll
            for (int q = 0; q < 4; q++) acc[mf][nf][q] = 0.f;

    #define G1_CP(c) do { \
        int _k0 = (c) * 32; \
        uint32_t _st = sb + (uint32_t)(((c) % 3) * 32768); \
        _Pragma("unroll") \
        for (int _it = 0; _it < 2; _it++) { \
            int _idx = tid + _it * 256; \
            int _r = _idx >> 2, _u = _idx & 3; \
            uint32_t _dst = _st + (uint32_t)(_r * 64) + SW64R(_r, _u * 16); \
            CP_ASYNC16(_dst,          g_xh + (m0 + _r) * C1 + _k0 + _u * 8); \
            CP_ASYNC16(_dst + 8192u,  g_xl + (m0 + _r) * C1 + _k0 + _u * 8); \
            CP_ASYNC16(_dst + 16384u, g_w1h + (long)(n0 + _r) * C1 + _k0 + _u * 8); \
            CP_ASYNC16(_dst + 24576u, g_w1l + (long)(n0 + _r) * C1 + _k0 + _u * 8); \
        } \
        CP_COMMIT(); \
    } while (0)

    G1_CP(0);
    G1_CP(1);
    for (int c = 0; c < 8; c++) {
        if (c == 7) { CP_WAIT0(); } else { CP_WAIT1(); }
        __syncthreads();
        if (c < 6) G1_CP(c + 2);
        uint32_t st = sb + (uint32_t)((c % 3) * 32768);
        consume32(st + aRow, st + 16384u + bRow, a_kb, a_xm, b_kb, b_xm, acc);
    }

    // store h1 + stats
    #pragma unroll
    for (int mf = 0; mf < 2; mf++) {
        const int lr0 = wr * 32 + mf * 16 + (lane >> 2);
        float* d0 = g_h1 + (m0 + lr0) * C1 + n0 + wc * 64 + 2 * (lane & 3);
        float* d1 = d0 + 8L * C1;
        #pragma unroll
        for (int nf = 0; nf < 8; nf++) {
            *(float2*)(d0 + nf * 8) = make_float2(acc[mf][nf][0], acc[mf][nf][1]);
            *(float2*)(d1 + nf * 8) = make_float2(acc[mf][nf][2], acc[mf][nf][3]);
        }
    }
    #pragma unroll
    for (int nf = 0; nf < 8; nf++) {
        #pragma unroll
        for (int par = 0; par < 2; par++) {
            float v0 = acc[0][nf][par], v1 = acc[0][nf][par + 2];
            float v2 = acc[1][nf][par], v3 = acc[1][nf][par + 2];
            float s = v0 + v1 + v2 + v3;
            float q = v0 * v0 + v1 * v1 + v2 * v2 + v3 * v3;
            #pragma unroll
            for (int m = 4; m <= 16; m <<= 1) {
                s += __shfl_xor_sync(0xffffffffu, s, m);
                q += __shfl_xor_sync(0xffffffffu, q, m);
            }
            if (lane < 4) {
                int ch = wc * 64 + nf * 8 + 2 * lane + par;
                atomicAdd(&ssum[ch], s);
                atomicAdd(&ssq[ch], q);
            }
        }
    }
    __syncthreads();
    if (tid < 128) {
        atomicAdd(&g_stats[n0 + tid], ssum[tid]);
        atomicAdd(&g_stats[256 + n0 + tid], ssq[tid]);
    }
}

// ---------------------------------------------------------------------------
__global__ void k_bnaff(const float* __restrict__ g, const float* __restrict__ b,
                        int C, int statoff, int affoff) {
    int o = threadIdx.x;
    if (o < C) {
        const float inv_cnt = 1.f / 131072.f;
        float mean = g_stats[statoff + o] * inv_cnt;
        float var  = g_stats[statoff + C + o] * inv_cnt - mean * mean;
        float sc = g[o] * rsqrtf(var + 1e-5f);
        g_aff[affoff + o]     = sc;
        g_aff[affoff + C + o] = b[o] - mean * sc;
    }
}

// ---------------------------------------------------------------------------
// K4: HMMA gemm2 (A 2-stage affine+split, B 3-stage cp.async, K=32 x8)
// ---------------------------------------------------------------------------
__global__ __launch_bounds__(256, 2) void k_gemm2h() {
    const uint32_t sb = smem_u32(dsm);
    const int tid = threadIdx.x;
    const int lane = tid & 31, wid = tid >> 5;
    const int wr = wid >> 1, wc = wid & 1;
    const long m0 = (long)blockIdx.x * 128;

    const int a_rin = (lane & 7) + ((lane >> 3) & 1) * 8;
    const int a_kb  = (lane >> 4) * 16;
    const int a_row = wr * 32 + a_rin;
    const uint32_t a_xm = (((uint32_t)a_rin >> 1) & 3u) << 4;
    const uint32_t aRow = (uint32_t)(a_row * 64);

    const int b_nin = (lane & 7) + (lane >= 16 ? 8 : 0);
    const int b_kb  = ((lane >> 3) & 1) * 16;
    const uint32_t b_xm = (((uint32_t)b_nin >> 1) & 3u) << 4;
    const uint32_t bRow = (uint32_t)((wc * 64 + b_nin) * 64);

    float* saff0 = (float*)(dsm + S2_AFF);
    float* saff1 = saff0 + 256;
    float* ssum  = (float*)(dsm + S2_SUM);
    float* ssq   = (float*)(dsm + S2_SQ);
    saff0[tid] = g_aff[tid];
    saff1[tid] = g_aff[256 + tid];
    if (tid < 128) { ssum[tid] = 0.f; ssq[tid] = 0.f; }
    __syncthreads();

    float acc[2][8][4];
    #pragma unroll
    for (int mf = 0; mf < 2; mf++)
        #pragma unroll
        for (int nf = 0; nf < 8; nf++)
            #pragma unroll
            for (int q = 0; q < 4; q++) acc[mf][nf][q] = 0.f;

    float4 v[4];

    #define G2_CPB(c) do { \
        int _k0 = (c) * 32; \
        uint32_t _st = sb + 32768u + (uint32_t)(((c) % 3) * 16384); \
        _Pragma("unroll") \
        for (int _it = 0; _it < 2; _it++) { \
            int _idx = tid + _it * 256; \
            int _r = _idx >> 2, _u = _idx & 3; \
            uint32_t _dst = _st + (uint32_t)(_r * 64) + SW64R(_r, _u * 16); \
            CP_ASYNC16(_dst,         g_w2h + (long)_r * C1 + _k0 + _u * 8); \
            CP_ASYNC16(_dst + 8192u, g_w2l + (long)_r * C1 + _k0 + _u * 8); \
        } \
        CP_COMMIT(); \
    } while (0)

    #define G2_LOADA(c) do { \
        int _k0 = (c) * 32; \
        _Pragma("unroll") \
        for (int _it = 0; _it < 4; _it++) { \
            int _idx = tid + _it * 256; \
            int _row = _idx >> 3, _cu = _idx & 7; \
            v[_it] = *(const float4*)(g_h1 + (m0 + _row) * C1 + _k0 + _cu * 4); \
        } \
    } while (0)

    #define G2_STOREA(c) do { \
        int _k0 = (c) * 32; \
        uint32_t _stoff = (uint32_t)(((c) & 1) * 16384); \
        _Pragma("unroll") \
        for (int _it = 0; _it < 4; _it++) { \
            int _idx = tid + _it * 256; \
            int _row = _idx >> 3, _cu = _idx & 7; \
            int _ch = _k0 + _cu * 4; \
            float4 _a = v[_it]; \
            _a.x = lrelu(saff0[_ch + 0] * _a.x + saff1[_ch + 0]); \
            _a.y = lrelu(saff0[_ch + 1] * _a.y + saff1[_ch + 1]); \
            _a.z = lrelu(saff0[_ch + 2] * _a.z + saff1[_ch + 2]); \
            _a.w = lrelu(saff0[_ch + 3] * _a.w + saff1[_ch + 3]); \
            uint32_t _h0 = prmt_hi(__float_as_uint(_a.x), __float_as_uint(_a.y)); \
            uint32_t _h1 = prmt_hi(__float_as_uint(_a.z), __float_as_uint(_a.w)); \
            uint32_t _l0 = cvt_bf16x2(_a.x - trunc_bf(_a.x), _a.y - trunc_bf(_a.y)); \
            uint32_t _l1 = cvt_bf16x2(_a.z - trunc_bf(_a.z), _a.w - trunc_bf(_a.w)); \
            uint32_t _off = _stoff + (uint32_t)(_row * 64) + \
                            SW64R(_row, (_cu >> 1) * 16) + (uint32_t)((_cu & 1) * 8); \
            *(uint2*)(dsm + _off)        = make_uint2(_h0, _h1); \
            *(uint2*)(dsm + 8192 + _off) = make_uint2(_l0, _l1); \
        } \
    } while (0)

    G2_CPB(0);
    G2_CPB(1);
    G2_LOADA(0);
    G2_STOREA(0);
    G2_LOADA(1);

    for (int c = 0; c < 8; c++) {
        if (c == 7) { CP_WAIT0(); } else { CP_WAIT1(); }
        __syncthreads();
        if (c < 6) G2_CPB(c + 2);
        uint32_t aHi = sb + (uint32_t)((c & 1) * 16384) + aRow;
        uint32_t bHi = sb + 32768u + (uint32_t)((c % 3) * 16384) + bRow;
        consume32(aHi, bHi, a_kb, a_xm, b_kb, b_xm, acc);
        if (c < 7) G2_STOREA(c + 1);
        if (c < 6) G2_LOADA(c + 2);
    }

    // store h2 + stats
    #pragma unroll
    for (int mf = 0; mf < 2; mf++) {
        const int lr0 = wr * 32 + mf * 16 + (lane >> 2);
        float* d0 = g_h2 + (m0 + lr0) * C2 + wc * 64 + 2 * (lane & 3);
        float* d1 = d0 + 8L * C2;
        #pragma unroll
        for (int nf = 0; nf < 8; nf++) {
            *(float2*)(d0 + nf * 8) = make_float2(acc[mf][nf][0], acc[mf][nf][1]);
            *(float2*)(d1 + nf * 8) = make_float2(acc[mf][nf][2], acc[mf][nf][3]);
        }
    }
    #pragma unroll
    for (int nf = 0; nf < 8; nf++) {
        #pragma unroll
        for (int par = 0; par < 2; par++) {
            float v0 = acc[0][nf][par], v1 = acc[0][nf][par + 2];
            float v2 = acc[1][nf][par], v3 = acc[1][nf][par + 2];
            float s = v0 + v1 + v2 + v3;
            float q = v0 * v0 + v1 * v1 + v2 * v2 + v3 * v3;
            #pragma unroll
            for (int m = 4; m <= 16; m <<= 1) {
                s += __shfl_xor_sync(0xffffffffu, s, m);
                q += __shfl_xor_sync(0xffffffffu, q, m);
            }
            if (lane < 4) {
                int ch = wc * 64 + nf * 8 + 2 * lane + par;
                atomicAdd(&ssum[ch], s);
                atomicAdd(&ssq[ch], q);
            }
        }
    }
    __syncthreads();
    if (tid < 128) {
        atomicAdd(&g_stats[512 + tid], ssum[tid]);
        atomicAdd(&g_stats[640 + tid], ssq[tid]);
    }
}

// ---------------------------------------------------------------------------
__global__ __launch_bounds__(256) void k_final(float* __restrict__ out) {
    long idx = ((long)blockIdx.x * blockDim.x + threadIdx.x);
    long e = idx * 4;
    int ch = (int)(e & 127);
    float4 v = *(const float4*)&g_h2[e];
    v.x = lrelu(g_aff[512 + ch + 0] * v.x + g_aff[640 + ch + 0]);
    v.y = lrelu(g_aff[512 + ch + 1] * v.y + g_aff[640 + ch + 1]);
    v.z = lrelu(g_aff[512 + ch + 2] * v.z + g_aff[640 + ch + 2]);
    v.w = lrelu(g_aff[512 + ch + 3] * v.w + g_aff[640 + ch + 3]);
    *(float4*)&out[e] = v;
}

// ---------------------------------------------------------------------------
extern "C" void kernel_launch(void* const* d_in, const int* in_sizes, int n_in,
                              void* d_out, int out_size) {
    const float* Ed = (const float*)d_in[0];
    const float* Ei = (const float*)d_in[1];
    const float* P  = (const float*)d_in[2];
    const float* W1 = (const float*)d_in[3];
    const float* g1 = (const float*)d_in[4];
    const float* b1 = (const float*)d_in[5];
    const float* W2 = (const float*)d_in[6];
    const float* g2 = (const float*)d_in[7];
    const float* b2 = (const float*)d_in[8];
    float* out = (float*)d_out;

    cudaFuncSetAttribute((const void*)k_aggr,
                         cudaFuncAttributeMaxDynamicSharedMemorySize, AG_TOT);
    cudaFuncSetAttribute((const void*)k_gemm1h,
                         cudaFuncAttributeMaxDynamicSharedMemorySize, SG_TOT);
    cudaFuncSetAttribute((const void*)k_gemm2h,
                         cudaFuncAttributeMaxDynamicSharedMemorySize, S2_TOT);

    k_zero<<<1, 768>>>();
    k_prep<<<dim3(16, 4, 256), 256>>>(P);
    k_wsplit<<<384, 256>>>(W1, W2);
    k_aggr<<<dim3(4, 256, 2), 256, AG_TOT>>>(Ed, Ei);
    k_gemm1h<<<dim3(2, 1024), 256, SG_TOT>>>();
    k_bnaff<<<1, 256>>>(g1, b1, 256, 0, 0);
    k_gemm2h<<<1024, 256, S2_TOT>>>();
    k_bnaff<<<1, 128>>>(g2, b2, 128, 512, 512);
    k_final<<<(int)(BN_ * C2 / 4 / 256), 256>>>(out);
}

// round 12
// speedup vs baseline: 2.1354x; 1.0277x over previous
#include <cuda_runtime.h>
#include <cuda_bf16.h>
#include <cstdint>

// Problem constants
#define BB   256
#define NN   512
#define DD   128
#define C1   256          // 2*D
#define C2   128
#define BN_  131072L      // BB*NN

// Scratch (device globals; no cudaMalloc allowed)
__device__ float g_h1[BN_ * C1];
__device__ float g_h2[BN_ * C2];
__device__ float g_stats[768];
__device__ float g_aff[768];
__device__ __nv_bfloat16 g_pt_hi[(long)BB * DD * NN];   // P^T hi, [b][d][j]
__device__ __nv_bfloat16 g_pt_lo[(long)BB * DD * NN];   // P^T lo
__device__ __nv_bfloat16 g_xh[BN_ * C1];                // xcat hi (bf16 split)
__device__ __nv_bfloat16 g_xl[BN_ * C1];                // xcat lo
__device__ __nv_bfloat16 g_w1h[C1 * C1];
__device__ __nv_bfloat16 g_w1l[C1 * C1];
__device__ __nv_bfloat16 g_w2h[C2 * C1];
__device__ __nv_bfloat16 g_w2l[C2 * C1];

__device__ __forceinline__ float lrelu(float v) { return v >= 0.f ? v : 0.01f * v; }

__device__ __forceinline__ uint32_t smem_u32(const void* p) {
    uint32_t a;
    asm("{ .reg .u64 t; cvta.to.shared.u64 t, %1; cvt.u32.u64 %0, t; }" : "=r"(a) : "l"(p));
    return a;
}

__device__ __forceinline__ uint32_t prmt_hi(uint32_t a, uint32_t b) {
    uint32_t r; asm("prmt.b32 %0, %1, %2, 0x7632;" : "=r"(r) : "r"(a), "r"(b)); return r;
}
__device__ __forceinline__ uint32_t cvt_bf16x2(float x, float y) {
    uint32_t r; asm("cvt.rn.bf16x2.f32 %0, %1, %2;" : "=r"(r) : "f"(y), "f"(x)); return r;
}
__device__ __forceinline__ float trunc_bf(float x) {
    return __uint_as_float(__float_as_uint(x) & 0xFFFF0000u);
}

#define LDMX4(r, addr) \
    asm volatile("ldmatrix.sync.aligned.m8n8.x4.shared.b16 {%0,%1,%2,%3}, [%4];" \
        : "=r"((r)[0]), "=r"((r)[1]), "=r"((r)[2]), "=r"((r)[3]) : "r"(addr))

#define MMA_BF16(d, a, b0v, b1v) \
    asm volatile("mma.sync.aligned.m16n8k16.row.col.f32.bf16.bf16.f32 " \
        "{%0,%1,%2,%3}, {%4,%5,%6,%7}, {%8,%9}, {%0,%1,%2,%3};" \
        : "+f"((d)[0]), "+f"((d)[1]), "+f"((d)[2]), "+f"((d)[3]) \
        : "r"((a)[0]), "r"((a)[1]), "r"((a)[2]), "r"((a)[3]), "r"(b0v), "r"(b1v))

#define CP_ASYNC16(dst, src) \
    asm volatile("cp.async.cg.shared.global [%0], [%1], 16;" :: "r"(dst), "l"(src) : "memory")
#define CP_COMMIT() asm volatile("cp.async.commit_group;" ::: "memory")
#define CP_WAIT0()  asm volatile("cp.async.wait_group 0;" ::: "memory")
#define CP_WAIT1()  asm volatile("cp.async.wait_group 1;" ::: "memory")
#define CP_WAIT2()  asm volatile("cp.async.wait_group 2;" ::: "memory")

// 64-byte-row tile swizzle: xor bits[4:6) with row bits[1:3)
#define SW64R(row, off) ((uint32_t)(off) ^ ((((uint32_t)(row) >> 1) & 3u) << 4))

// ---- smem layouts (K=32 tiles: 128 rows x 64 B; hi at +0, lo at +8192) ----
// aggr: A stages 0,16384; B stages 32768 + (c&3)*16384
#define AG_SRS     98304
#define AG_SRINV   98816
#define AG_TOT     99328
// gemm1h: stages (c%3)*32768: A_HI+0, A_LO+8192, B_HI+16384, B_LO+24576
#define SG_SUM  98304
#define SG_SQ   98816
#define SG_TOT  99328
// gemm2h: A 0,16384; B 32768+(c&3)*16384
#define S2_AFF  98304
#define S2_SUM  100352
#define S2_SQ   100864
#define S2_TOT  101376

extern __shared__ __align__(1024) char dsm[];

// ---------------------------------------------------------------------------
// consume32: one K=32 chunk, 3-pass bf16-split HMMA, pass-major ordering.
// ---------------------------------------------------------------------------
__device__ __forceinline__ void consume32(uint32_t aHi, uint32_t bHi,
                                          int a_kb, uint32_t a_xm,
                                          int b_kb, uint32_t b_xm,
                                          float (&acc)[2][8][4]) {
    #pragma unroll
    for (int ks = 0; ks < 2; ks++) {
        const uint32_t kA = ((uint32_t)(ks * 32 + a_kb)) ^ a_xm;
        uint32_t ah[2][4], al[2][4];
        LDMX4(ah[0], aHi + kA);
        LDMX4(ah[1], aHi + 1024 + kA);
        LDMX4(al[0], aHi + 8192 + kA);
        LDMX4(al[1], aHi + 8192 + 1024 + kA);

        const uint32_t kB = ((uint32_t)(ks * 32 + b_kb)) ^ b_xm;
        #pragma unroll
        for (int nh = 0; nh < 2; nh++) {
            uint32_t bh[2][4], bl[2][4];
            LDMX4(bh[0], bHi + (uint32_t)(nh * 2048) + kB);
            LDMX4(bh[1], bHi + (uint32_t)(nh * 2048 + 1024) + kB);
            LDMX4(bl[0], bHi + 8192u + (uint32_t)(nh * 2048) + kB);
            LDMX4(bl[1], bHi + 8192u + (uint32_t)(nh * 2048 + 1024) + kB);
            // pass 1: Ah * Bh (8 MMAs)
            #pragma unroll
            for (int nf4 = 0; nf4 < 4; nf4++) {
                const int qq = nf4 >> 1, hh = (nf4 & 1) * 2;
                const int nf = nh * 4 + nf4;
                MMA_BF16(acc[0][nf], ah[0], bh[qq][hh], bh[qq][hh + 1]);
                MMA_BF16(acc[1][nf], ah[1], bh[qq][hh], bh[qq][hh + 1]);
            }
            // pass 2: Ah * Bl
            #pragma unroll
            for (int nf4 = 0; nf4 < 4; nf4++) {
                const int qq = nf4 >> 1, hh = (nf4 & 1) * 2;
                const int nf = nh * 4 + nf4;
                MMA_BF16(acc[0][nf], ah[0], bl[qq][hh], bl[qq][hh + 1]);
                MMA_BF16(acc[1][nf], ah[1], bl[qq][hh], bl[qq][hh + 1]);
            }
            // pass 3: Al * Bh
            #pragma unroll
            for (int nf4 = 0; nf4 < 4; nf4++) {
                const int qq = nf4 >> 1, hh = (nf4 & 1) * 2;
                const int nf = nh * 4 + nf4;
                MMA_BF16(acc[0][nf], al[0], bh[qq][hh], bh[qq][hh + 1]);
                MMA_BF16(acc[1][nf], al[1], bh[qq][hh], bh[qq][hh + 1]);
            }
        }
    }
}

// ---------------------------------------------------------------------------
__global__ void k_zero() {
    int t = threadIdx.x;
    if (t < 768) g_stats[t] = 0.f;
}

// ---------------------------------------------------------------------------
__global__ __launch_bounds__(256) void k_prep(const float* __restrict__ P) {
    __shared__ float s[32][33];
    int b = blockIdx.z, j0 = blockIdx.x * 32, d0 = blockIdx.y * 32;
    int t = threadIdx.x;
    {
        int jr = t >> 3, dq = (t & 7) * 4;
        float4 v = *(const float4*)(P + ((long)b * NN + j0 + jr) * DD + d0 + dq);
        s[jr][dq + 0] = v.x; s[jr][dq + 1] = v.y; s[jr][dq + 2] = v.z; s[jr][dq + 3] = v.w;
    }
    __syncthreads();
    int d = t >> 3, jq = (t & 7) * 4;
    float x0 = s[jq + 0][d], x1 = s[jq + 1][d], x2 = s[jq + 2][d], x3 = s[jq + 3][d];
    uint32_t h01 = prmt_hi(__float_as_uint(x0), __float_as_uint(x1));
    uint32_t h23 = prmt_hi(__float_as_uint(x2), __float_as_uint(x3));
    uint32_t l01 = cvt_bf16x2(x0 - trunc_bf(x0), x1 - trunc_bf(x1));
    uint32_t l23 = cvt_bf16x2(x2 - trunc_bf(x2), x3 - trunc_bf(x3));
    long off = ((long)b * DD + d0 + d) * NN + j0 + jq;
    *(uint2*)(g_pt_hi + off) = make_uint2(h01, h23);
    *(uint2*)(g_pt_lo + off) = make_uint2(l01, l23);
}

// ---------------------------------------------------------------------------
__global__ __launch_bounds__(256) void k_wsplit(const float* __restrict__ W1,
                                                const float* __restrict__ W2) {
    int i = blockIdx.x * 256 + threadIdx.x;
    if (i < C1 * C1) {
        float f = W1[i];
        ((unsigned short*)g_w1h)[i] = (unsigned short)(__float_as_uint(f) >> 16);
        g_w1l[i] = __float2bfloat16(f - trunc_bf(f));
    } else if (i < C1 * C1 + C2 * C1) {
        int j = i - C1 * C1;
        float f = W2[j];
        ((unsigned short*)g_w2h)[j] = (unsigned short)(__float_as_uint(f) >> 16);
        g_w2l[j] = __float2bfloat16(f - trunc_bf(f));
    }
}

// ---------------------------------------------------------------------------
// K1: deep-pipelined bf16-split HMMA aggr. K=32 x16 chunks.
//  A 2-stage STS (mask+split), B 4-stage cp.async (3-chunk lookahead).
// ---------------------------------------------------------------------------
__global__ __launch_bounds__(256, 2) void k_aggr(const float* __restrict__ Ed,
                                                 const float* __restrict__ Ei) {
    const uint32_t sb = smem_u32(dsm);
    const int tid = threadIdx.x;
    const int lane = tid & 31, wid = tid >> 5;
    const int wr = wid >> 1, wc = wid & 1;
    const int b = blockIdx.y, i0 = blockIdx.x * 128, edge = blockIdx.z;
    const float* Ebase = (edge ? Ei : Ed) + ((long)b * NN + i0) * NN;

    // ---- hoisted per-thread invariants ----
    const int e_row = tid >> 3, e_cu = tid & 7;                  // E load/store map
    const float* eP = Ebase + (long)e_row * NN + e_cu * 4;
    const uint32_t sA_off = (uint32_t)(e_row * 64) + SW64R(e_row, (e_cu >> 1) * 16)
                          + (uint32_t)((e_cu & 1) * 8);
    const int b_d = tid >> 2, b_u = tid & 3;                     // B cp map
    const __nv_bfloat16* cpsh = g_pt_hi + (long)b * DD * NN + (long)b_d * NN + b_u * 8;
    const __nv_bfloat16* cpsl = g_pt_lo + (long)b * DD * NN + (long)b_d * NN + b_u * 8;
    const uint32_t cpd = (uint32_t)(b_d * 64) + SW64R(b_d, b_u * 16);

    // consumer lane addressing
    const int a_rin = (lane & 7) + ((lane >> 3) & 1) * 8;
    const int a_kb  = (lane >> 4) * 16;
    const int a_row = wr * 32 + a_rin;
    const uint32_t a_xm = (((uint32_t)a_rin >> 1) & 3u) << 4;
    const uint32_t aRow = (uint32_t)(a_row * 64);
    const int b_nin = (lane & 7) + (lane >= 16 ? 8 : 0);
    const int b_kb  = ((lane >> 3) & 1) * 16;
    const uint32_t b_xm = (((uint32_t)b_nin >> 1) & 3u) << 4;
    const uint32_t bRow = (uint32_t)((wc * 64 + b_nin) * 64);

    float acc[2][8][4];
    #pragma unroll
    for (int mf = 0; mf < 2; mf++)
        #pragma unroll
        for (int nf = 0; nf < 8; nf++)
            #pragma unroll
            for (int q = 0; q < 4; q++) acc[mf][nf][q] = 0.f;

    float rs[4];
    #pragma unroll
    for (int i = 0; i < 4; i++) rs[i] = 0.f;
    float4 v[4];

    #define AGGR_CPB(c) do { \
        uint32_t _st = sb + 32768u + (uint32_t)(((c) & 3) * 16384); \
        _Pragma("unroll") \
        for (int _it = 0; _it < 2; _it++) { \
            uint32_t _dst = _st + cpd + (uint32_t)(_it * 4096); \
            CP_ASYNC16(_dst,         cpsh + (long)_it * 64 * NN + (c) * 32); \
            CP_ASYNC16(_dst + 8192u, cpsl + (long)_it * 64 * NN + (c) * 32); \
        } \
        CP_COMMIT(); \
    } while (0)

    #define AGGR_LOADE(c) do { \
        _Pragma("unroll") \
        for (int _it = 0; _it < 4; _it++) \
            v[_it] = *(const float4*)(eP + (long)_it * 32 * NN + (c) * 32); \
    } while (0)

    #define AGGR_STOREE(c) do { \
        uint32_t _soff = (uint32_t)(((c) & 1) * 16384) + sA_off; \
        int _jb = (c) * 32 + e_cu * 4; \
        _Pragma("unroll") \
        for (int _it = 0; _it < 4; _it++) { \
            int _irow = i0 + e_row + _it * 32; \
            float4 _a = v[_it]; \
            if (_jb + 0 == _irow) _a.x = 0.f; \
            if (_jb + 1 == _irow) _a.y = 0.f; \
            if (_jb + 2 == _irow) _a.z = 0.f; \
            if (_jb + 3 == _irow) _a.w = 0.f; \
            rs[_it] += _a.x + _a.y + _a.z + _a.w; \
            uint32_t _h0 = prmt_hi(__float_as_uint(_a.x), __float_as_uint(_a.y)); \
            uint32_t _h1 = prmt_hi(__float_as_uint(_a.z), __float_as_uint(_a.w)); \
            uint32_t _l0 = cvt_bf16x2(_a.x - trunc_bf(_a.x), _a.y - trunc_bf(_a.y)); \
            uint32_t _l1 = cvt_bf16x2(_a.z - trunc_bf(_a.z), _a.w - trunc_bf(_a.w)); \
            uint32_t _off = _soff + (uint32_t)(_it * 2048); \
            *(uint2*)(dsm + _off)        = make_uint2(_h0, _h1); \
            *(uint2*)(dsm + 8192 + _off) = make_uint2(_l0, _l1); \
        } \
    } while (0)

    // prologue
    AGGR_CPB(0); AGGR_CPB(1); AGGR_CPB(2);
    AGGR_LOADE(0);
    AGGR_STOREE(0);
    AGGR_LOADE(1);

    #pragma unroll 4
    for (int c = 0; c < 16; c++) {
        if (c < 14) { CP_WAIT2(); } else if (c == 14) { CP_WAIT1(); } else { CP_WAIT0(); }
        __syncthreads();
        if (c < 13) AGGR_CPB(c + 3);
        if (c < 15) AGGR_STOREE(c + 1);
        if (c < 14) AGGR_LOADE(c + 2);
        uint32_t aHi = sb + (uint32_t)((c & 1) * 16384) + aRow;
        uint32_t bHi = sb + 32768u + (uint32_t)((c & 3) * 16384) + bRow;
        consume32(aHi, bHi, a_kb, a_xm, b_kb, b_xm, acc);
    }

    // rowsum reduce: 8 consecutive threads share a row
    __syncthreads();
    float* srs = (float*)(dsm + AG_SRS);
    #pragma unroll
    for (int it = 0; it < 4; it++) {
        float s = rs[it];
        #pragma unroll
        for (int m = 1; m <= 4; m <<= 1) s += __shfl_xor_sync(0xffffffffu, s, m);
        if ((lane & 7) == 0) srs[(tid >> 3) + it * 32] = s;
    }
    __syncthreads();
    float* rinv = (float*)(dsm + AG_SRINV);
    if (tid < 128) rinv[tid] = 1.f / fmaxf(srs[tid], 1e-12f);
    __syncthreads();

    // epilogue: scale + split bf16 store
    #pragma unroll
    for (int mf = 0; mf < 2; mf++) {
        const int lr0 = wr * 32 + mf * 16 + (lane >> 2);
        const float inv0 = rinv[lr0], inv1 = rinv[lr0 + 8];
        long idx0 = ((long)(b * NN + i0 + lr0)) * C1 + edge * 128 + wc * 64 + 2 * (lane & 3);
        long idx1 = idx0 + 8L * C1;
        #pragma unroll
        for (int nf = 0; nf < 8; nf++) {
            float x0 = acc[mf][nf][0] * inv0, x1 = acc[mf][nf][1] * inv0;
            float y0 = acc[mf][nf][2] * inv1, y1 = acc[mf][nf][3] * inv1;
            *(uint32_t*)(g_xh + idx0 + nf * 8) = prmt_hi(__float_as_uint(x0), __float_as_uint(x1));
            *(uint32_t*)(g_xl + idx0 + nf * 8) = cvt_bf16x2(x0 - trunc_bf(x0), x1 - trunc_bf(x1));
            *(uint32_t*)(g_xh + idx1 + nf * 8) = prmt_hi(__float_as_uint(y0), __float_as_uint(y1));
            *(uint32_t*)(g_xl + idx1 + nf * 8) = cvt_bf16x2(y0 - trunc_bf(y0), y1 - trunc_bf(y1));
        }
    }
}

// ---------------------------------------------------------------------------
// K2: HMMA gemm1 (3-stage all-cp.async pipeline, K=32 x8 chunks) + BN stats
// ---------------------------------------------------------------------------
__global__ __launch_bounds__(256, 2) void k_gemm1h() {
    const uint32_t sb = smem_u32(dsm);
    const int tid = threadIdx.x;
    const int lane = tid & 31, wid = tid >> 5;
    const int wr = wid >> 1, wc = wid & 1;
    const long m0 = (long)blockIdx.y * 128;
    const int n0 = blockIdx.x * 128;

    const int g_r = tid >> 2, g_u = tid & 3;
    const __nv_bfloat16* sxh = g_xh + (m0 + g_r) * C1 + g_u * 8;
    const __nv_bfloat16* sxl = g_xl + (m0 + g_r) * C1 + g_u * 8;
    const __nv_bfloat16* swh = g_w1h + (long)(n0 + g_r) * C1 + g_u * 8;
    const __nv_bfloat16* swl = g_w1l + (long)(n0 + g_r) * C1 + g_u * 8;
    const uint32_t cpd = (uint32_t)(g_r * 64) + SW64R(g_r, g_u * 16);

    const int a_rin = (lane & 7) + ((lane >> 3) & 1) * 8;
    const int a_kb  = (lane >> 4) * 16;
    const int a_row = wr * 32 + a_rin;
    const uint32_t a_xm = (((uint32_t)a_rin >> 1) & 3u) << 4;
    const uint32_t aRow = (uint32_t)(a_row * 64);
    const int b_nin = (lane & 7) + (lane >= 16 ? 8 : 0);
    const int b_kb  = ((lane >> 3) & 1) * 16;
    const uint32_t b_xm = (((uint32_t)b_nin >> 1) & 3u) << 4;
    const uint32_t bRow = (uint32_t)((wc * 64 + b_nin) * 64);

    float* ssum = (float*)(dsm + SG_SUM);
    float* ssq  = (float*)(dsm + SG_SQ);
    if (tid < 128) { ssum[tid] = 0.f; ssq[tid] = 0.f; }

    float acc[2][8][4];
    #pragma unroll
    for (int mf = 0; mf < 2; mf++)
        #pragma unroll
        for (int nf = 0; nf < 8; nf++)
            #pragma unroll
            for (int q = 0; q < 4; q++) acc[mf][nf][q] = 0.f;

    #define G1_CP(c) do { \
        uint32_t _st = sb + (uint32_t)(((c) % 3) * 32768); \
        _Pragma("unroll") \
        for (int _it = 0; _it < 2; _it++) { \
            uint32_t _dst = _st + cpd + (uint32_t)(_it * 4096); \
            CP_ASYNC16(_dst,          sxh + (long)_it * 64 * C1 + (c) * 32); \
            CP_ASYNC16(_dst + 8192u,  sxl + (long)_it * 64 * C1 + (c) * 32); \
            CP_ASYNC16(_dst + 16384u, swh + (long)_it * 64 * C1 + (c) * 32); \
            CP_ASYNC16(_dst + 24576u, swl + (long)_it * 64 * C1 + (c) * 32); \
        } \
        CP_COMMIT(); \
    } while (0)

    G1_CP(0);
    G1_CP(1);
    #pragma unroll
    for (int c = 0; c < 8; c++) {
        if (c < 7) { CP_WAIT1(); } else { CP_WAIT0(); }
        __syncthreads();
        if (c < 6) G1_CP(c + 2);
        uint32_t st = sb + (uint32_t)((c % 3) * 32768);
        consume32(st + aRow, st + 16384u + bRow, a_kb, a_xm, b_kb, b_xm, acc);
    }

    // store h1 + stats
    #pragma unroll
    for (int mf = 0; mf < 2; mf++) {
        const int lr0 = wr * 32 + mf * 16 + (lane >> 2);
        float* d0 = g_h1 + (m0 + lr0) * C1 + n0 + wc * 64 + 2 * (lane & 3);
        float* d1 = d0 + 8L * C1;
        #pragma unroll
        for (int nf = 0; nf < 8; nf++) {
            *(float2*)(d0 + nf * 8) = make_float2(acc[mf][nf][0], acc[mf][nf][1]);
            *(float2*)(d1 + nf * 8) = make_float2(acc[mf][nf][2], acc[mf][nf][3]);
        }
    }
    #pragma unroll
    for (int nf = 0; nf < 8; nf++) {
        #pragma unroll
        for (int par = 0; par < 2; par++) {
            float v0 = acc[0][nf][par], v1 = acc[0][nf][par + 2];
            float v2 = acc[1][nf][par], v3 = acc[1][nf][par + 2];
            float s = v0 + v1 + v2 + v3;
            float q = v0 * v0 + v1 * v1 + v2 * v2 + v3 * v3;
            #pragma unroll
            for (int m = 4; m <= 16; m <<= 1) {
                s += __shfl_xor_sync(0xffffffffu, s, m);
                q += __shfl_xor_sync(0xffffffffu, q, m);
            }
            if (lane < 4) {
                int ch = wc * 64 + nf * 8 + 2 * lane + par;
                atomicAdd(&ssum[ch], s);
                atomicAdd(&ssq[ch], q);
            }
        }
    }
    __syncthreads();
    if (tid < 128) {
        atomicAdd(&g_stats[n0 + tid], ssum[tid]);
        atomicAdd(&g_stats[256 + n0 + tid], ssq[tid]);
    }
}

// ---------------------------------------------------------------------------
__global__ void k_bnaff(const float* __restrict__ g, const float* __restrict__ b,
                        int C, int statoff, int affoff) {
    int o = threadIdx.x;
    if (o < C) {
        const float inv_cnt = 1.f / 131072.f;
        float mean = g_stats[statoff + o] * inv_cnt;
        float var  = g_stats[statoff + C + o] * inv_cnt - mean * mean;
        float sc = g[o] * rsqrtf(var + 1e-5f);
        g_aff[affoff + o]     = sc;
        g_aff[affoff + C + o] = b[o] - mean * sc;
    }
}

// ---------------------------------------------------------------------------
// K4: HMMA gemm2 (A 2-stage affine+split, B 4-stage cp.async, K=32 x8)
// ---------------------------------------------------------------------------
__global__ __launch_bounds__(256, 2) void k_gemm2h() {
    const uint32_t sb = smem_u32(dsm);
    const int tid = threadIdx.x;
    const int lane = tid & 31, wid = tid >> 5;
    const int wr = wid >> 1, wc = wid & 1;
    const long m0 = (long)blockIdx.x * 128;

    const int e_row = tid >> 3, e_cu = tid & 7;
    const float* aP = g_h1 + (m0 + e_row) * C1 + e_cu * 4;
    const uint32_t sA_off = (uint32_t)(e_row * 64) + SW64R(e_row, (e_cu >> 1) * 16)
                          + (uint32_t)((e_cu & 1) * 8);
    const int b_d = tid >> 2, b_u = tid & 3;
    const __nv_bfloat16* cpsh = g_w2h + (long)b_d * C1 + b_u * 8;
    const __nv_bfloat16* cpsl = g_w2l + (long)b_d * C1 + b_u * 8;
    const uint32_t cpd = (uint32_t)(b_d * 64) + SW64R(b_d, b_u * 16);

    const int a_rin = (lane & 7) + ((lane >> 3) & 1) * 8;
    const int a_kb  = (lane >> 4) * 16;
    const int a_row = wr * 32 + a_rin;
    const uint32_t a_xm = (((uint32_t)a_rin >> 1) & 3u) << 4;
    const uint32_t aRow = (uint32_t)(a_row * 64);
    const int b_nin = (lane & 7) + (lane >= 16 ? 8 : 0);
    const int b_kb  = ((lane >> 3) & 1) * 16;
    const uint32_t b_xm = (((uint32_t)b_nin >> 1) & 3u) << 4;
    const uint32_t bRow = (uint32_t)((wc * 64 + b_nin) * 64);

    float* saff0 = (float*)(dsm + S2_AFF);
    float* saff1 = saff0 + 256;
    float* ssum  = (float*)(dsm + S2_SUM);
    float* ssq   = (float*)(dsm + S2_SQ);
    saff0[tid] = g_aff[tid];
    saff1[tid] = g_aff[256 + tid];
    if (tid < 128) { ssum[tid] = 0.f; ssq[tid] = 0.f; }
    __syncthreads();

    float acc[2][8][4];
    #pragma unroll
    for (int mf = 0; mf < 2; mf++)
        #pragma unroll
        for (int nf = 0; nf < 8; nf++)
            #pragma unroll
            for (int q = 0; q < 4; q++) acc[mf][nf][q] = 0.f;

    float4 v[4];

    #define G2_CPB(c) do { \
        uint32_t _st = sb + 32768u + (uint32_t)(((c) & 3) * 16384); \
        CP_ASYNC16(_st + cpd,         cpsh + (c) * 32); \
        CP_ASYNC16(_st + cpd + 8192u, cpsl + (c) * 32); \
        CP_COMMIT(); \
    } while (0)

    #define G2_LOADA(c) do { \
        _Pragma("unroll") \
        for (int _it = 0; _it < 4; _it++) \
            v[_it] = *(const float4*)(aP + (long)_it * 32 * C1 + (c) * 32); \
    } while (0)

    #define G2_STOREA(c) do { \
        uint32_t _soff = (uint32_t)(((c) & 1) * 16384) + sA_off; \
        int _ch = (c) * 32 + e_cu * 4; \
        _Pragma("unroll") \
        for (int _it = 0; _it < 4; _it++) { \
            float4 _a = v[_it]; \
            _a.x = lrelu(saff0[_ch + 0] * _a.x + saff1[_ch + 0]); \
            _a.y = lrelu(saff0[_ch + 1] * _a.y + saff1[_ch + 1]); \
            _a.z = lrelu(saff0[_ch + 2] * _a.z + saff1[_ch + 2]); \
            _a.w = lrelu(saff0[_ch + 3] * _a.w + saff1[_ch + 3]); \
            uint32_t _h0 = prmt_hi(__float_as_uint(_a.x), __float_as_uint(_a.y)); \
            uint32_t _h1 = prmt_hi(__float_as_uint(_a.z), __float_as_uint(_a.w)); \
            uint32_t _l0 = cvt_bf16x2(_a.x - trunc_bf(_a.x), _a.y - trunc_bf(_a.y)); \
            uint32_t _l1 = cvt_bf16x2(_a.z - trunc_bf(_a.z), _a.w - trunc_bf(_a.w)); \
            uint32_t _off = _soff + (uint32_t)(_it * 2048); \
            *(uint2*)(dsm + _off)        = make_uint2(_h0, _h1); \
            *(uint2*)(dsm + 8192 + _off) = make_uint2(_l0, _l1); \
        } \
    } while (0)

    // b_d covers only rows 0..63 of B (C2=128 n-rows): second half via tid+256 mapping
    // -> B tile is 128 rows; with 256 threads and 1 cp-iter we cover 64 rows * 4 u.
    //   Use two cp iterations like aggr: rows b_d and b_d+64.
    #undef G2_CPB
    #define G2_CPB(c) do { \
        uint32_t _st = sb + 32768u + (uint32_t)(((c) & 3) * 16384); \
        _Pragma("unroll") \
        for (int _it = 0; _it < 2; _it++) { \
            uint32_t _dst = _st + cpd + (uint32_t)(_it * 4096); \
            CP_ASYNC16(_dst,         cpsh + (long)_it * 64 * C1 + (c) * 32); \
            CP_ASYNC16(_dst + 8192u, cpsl + (long)_it * 64 * C1 + (c) * 32); \
        } \
        CP_COMMIT(); \
    } while (0)

    G2_CPB(0); G2_CPB(1); G2_CPB(2);
    G2_LOADA(0);
    G2_STOREA(0);
    G2_LOADA(1);

    #pragma unroll
    for (int c = 0; c < 8; c++) {
        if (c < 6) { CP_WAIT2(); } else if (c == 6) { CP_WAIT1(); } else { CP_WAIT0(); }
        __syncthreads();
        if (c < 5) G2_CPB(c + 3);
        if (c < 7) G2_STOREA(c + 1);
        if (c < 6) G2_LOADA(c + 2);
        uint32_t aHi = sb + (uint32_t)((c & 1) * 16384) + aRow;
        uint32_t bHi = sb + 32768u + (uint32_t)((c & 3) * 16384) + bRow;
        consume32(aHi, bHi, a_kb, a_xm, b_kb, b_xm, acc);
    }

    // store h2 + stats
    #pragma unroll
    for (int mf = 0; mf < 2; mf++) {
        const int lr0 = wr * 32 + mf * 16 + (lane >> 2);
        float* d0 = g_h2 + (m0 + lr0) * C2 + wc * 64 + 2 * (lane & 3);
        float* d1 = d0 + 8L * C2;
        #pragma unroll
        for (int nf = 0; nf < 8; nf++) {
            *(float2*)(d0 + nf * 8) = make_float2(acc[mf][nf][0], acc[mf][nf][1]);
            *(float2*)(d1 + nf * 8) = make_float2(acc[mf][nf][2], acc[mf][nf][3]);
        }
    }
    #pragma unroll
    for (int nf = 0; nf < 8; nf++) {
        #pragma unroll
        for (int par = 0; par < 2; par++) {
            float v0 = acc[0][nf][par], v1 = acc[0][nf][par + 2];
            float v2 = acc[1][nf][par], v3 = acc[1][nf][par + 2];
            float s = v0 + v1 + v2 + v3;
            float q = v0 * v0 + v1 * v1 + v2 * v2 + v3 * v3;
            #pragma unroll
            for (int m = 4; m <= 16; m <<= 1) {
                s += __shfl_xor_sync(0xffffffffu, s, m);
                q += __shfl_xor_sync(0xffffffffu, q, m);
            }
            if (lane < 4) {
                int ch = wc * 64 + nf * 8 + 2 * lane + par;
                atomicAdd(&ssum[ch], s);
                atomicAdd(&ssq[ch], q);
            }
        }
    }
    __syncthreads();
    if (tid < 128) {
        atomicAdd(&g_stats[512 + tid], ssum[tid]);
        atomicAdd(&g_stats[640 + tid], ssq[tid]);
    }
}

// ---------------------------------------------------------------------------
__global__ __launch_bounds__(256) void k_final(float* __restrict__ out) {
    long idx = ((long)blockIdx.x * blockDim.x + threadIdx.x);
    long e = idx * 4;
    int ch = (int)(e & 127);
    float4 v = *(const float4*)&g_h2[e];
    v.x = lrelu(g_aff[512 + ch + 0] * v.x + g_aff[640 + ch + 0]);
    v.y = lrelu(g_aff[512 + ch + 1] * v.y + g_aff[640 + ch + 1]);
    v.z = lrelu(g_aff[512 + ch + 2] * v.z + g_aff[640 + ch + 2]);
    v.w = lrelu(g_aff[512 + ch + 3] * v.w + g_aff[640 + ch + 3]);
    *(float4*)&out[e] = v;
}

// ---------------------------------------------------------------------------
extern "C" void kernel_launch(void* const* d_in, const int* in_sizes, int n_in,
                              void* d_out, int out_size) {
    const float* Ed = (const float*)d_in[0];
    const float* Ei = (const float*)d_in[1];
    const float* P  = (const float*)d_in[2];
    const float* W1 = (const float*)d_in[3];
    const float* g1 = (const float*)d_in[4];
    const float* b1 = (const float*)d_in[5];
    const float* W2 = (const float*)d_in[6];
    const float* g2 = (const float*)d_in[7];
    const float* b2 = (const float*)d_in[8];
    float* out = (float*)d_out;

    cudaFuncSetAttribute((const void*)k_aggr,
                         cudaFuncAttributeMaxDynamicSharedMemorySize, AG_TOT);
    cudaFuncSetAttribute((const void*)k_gemm1h,
                         cudaFuncAttributeMaxDynamicSharedMemorySize, SG_TOT);
    cudaFuncSetAttribute((const void*)k_gemm2h,
                         cudaFuncAttributeMaxDynamicSharedMemorySize, S2_TOT);

    k_zero<<<1, 768>>>();
    k_prep<<<dim3(16, 4, 256), 256>>>(P);
    k_wsplit<<<384, 256>>>(W1, W2);
    k_aggr<<<dim3(4, 256, 2), 256, AG_TOT>>>(Ed, Ei);
    k_gemm1h<<<dim3(2, 1024), 256, SG_TOT>>>();
    k_bnaff<<<1, 256>>>(g1, b1, 256, 0, 0);
    k_gemm2h<<<1024, 256, S2_TOT>>>();
    k_bnaff<<<1, 128>>>(g2, b2, 128, 512, 512);
    k_final<<<(int)(BN_ * C2 / 4 / 256), 256>>>(out);
}